// round 11
// baseline (speedup 1.0000x reference)
#include <cuda_runtime.h>
#include <cuda_bf16.h>
#include <cstdint>
#include <math.h>

// Problem constants
#define B_    2
#define S_    2048
#define DIM_  2048
#define H_    16
#define DH_   128
#define MROWS (B_ * S_)   // 4096

// ---------------------------------------------------------------------------
// Scratch (allocation-free rule: device globals)
// ---------------------------------------------------------------------------
__device__ __nv_bfloat16 g_xhi [MROWS * DIM_];
__device__ __nv_bfloat16 g_xlo [MROWS * DIM_];
__device__ __nv_bfloat16 g_wqhi[DIM_ * DIM_];
__device__ __nv_bfloat16 g_wqlo[DIM_ * DIM_];
__device__ __nv_bfloat16 g_wkhi[DIM_ * DIM_];
__device__ __nv_bfloat16 g_wklo[DIM_ * DIM_];
__device__ __nv_bfloat16 g_wvhi[DIM_ * DIM_];
__device__ __nv_bfloat16 g_wvlo[DIM_ * DIM_];
__device__ __nv_bfloat16 g_wohi[DIM_ * DIM_];
__device__ __nv_bfloat16 g_wolo[DIM_ * DIM_];
__device__ __nv_bfloat16 g_qhi [MROWS * DIM_];
__device__ __nv_bfloat16 g_qlo [MROWS * DIM_];
__device__ __nv_bfloat16 g_khi [MROWS * DIM_];
__device__ __nv_bfloat16 g_klo [MROWS * DIM_];
__device__ __nv_bfloat16 g_vhi [MROWS * DIM_];
__device__ __nv_bfloat16 g_vlo [MROWS * DIM_];
__device__ __nv_bfloat16 g_othi[MROWS * DIM_];
__device__ __nv_bfloat16 g_otlo[MROWS * DIM_];

// ---------------------------------------------------------------------------
// Helpers
// ---------------------------------------------------------------------------
__device__ __forceinline__ uint32_t smem_u32(const void* p) {
    uint32_t a;
    asm("{ .reg .u64 t; cvta.to.shared.u64 t, %1; cvt.u32.u64 %0, t; }" : "=r"(a) : "l"(p));
    return a;
}
__device__ __forceinline__ void cp_async16(uint32_t dst, const void* src) {
    asm volatile("cp.async.cg.shared.global [%0], [%1], 16;" :: "r"(dst), "l"(src));
}
#define CP_COMMIT() asm volatile("cp.async.commit_group;" ::: "memory")
#define CP_WAIT(n)  asm volatile("cp.async.wait_group %0;" :: "n"(n) : "memory")

__device__ __forceinline__ void ldmatrix_x4(uint32_t& r0, uint32_t& r1,
                                            uint32_t& r2, uint32_t& r3, uint32_t addr) {
    asm volatile("ldmatrix.sync.aligned.m8n8.x4.shared.b16 {%0,%1,%2,%3}, [%4];"
                 : "=r"(r0), "=r"(r1), "=r"(r2), "=r"(r3) : "r"(addr));
}
__device__ __forceinline__ void ldmatrix_x4_trans(uint32_t& r0, uint32_t& r1,
                                                  uint32_t& r2, uint32_t& r3, uint32_t addr) {
    asm volatile("ldmatrix.sync.aligned.m8n8.x4.trans.shared.b16 {%0,%1,%2,%3}, [%4];"
                 : "=r"(r0), "=r"(r1), "=r"(r2), "=r"(r3) : "r"(addr));
}
__device__ __forceinline__ void mma_bf16(float* c, const uint32_t* a, const uint32_t* b) {
    asm volatile(
        "mma.sync.aligned.m16n8k16.row.col.f32.bf16.bf16.f32 "
        "{%0,%1,%2,%3}, {%4,%5,%6,%7}, {%8,%9}, {%0,%1,%2,%3};"
        : "+f"(c[0]), "+f"(c[1]), "+f"(c[2]), "+f"(c[3])
        : "r"(a[0]), "r"(a[1]), "r"(a[2]), "r"(a[3]), "r"(b[0]), "r"(b[1]));
}

// Fast exp2 (degree-5 poly on FMA pipe, avoids MUFU bottleneck)
__device__ __forceinline__ float fexp2(float x) {
    x = fmaxf(x, -80.f);
    float f = x + 12582912.f;
    int  n  = __float_as_int(f) - 0x4B400000;
    float r = x - (f - 12582912.f);
    float p =            1.3333558146e-3f;
    p = fmaf(p, r, 9.6181291076e-3f);
    p = fmaf(p, r, 5.5504108665e-2f);
    p = fmaf(p, r, 2.4022650696e-1f);
    p = fmaf(p, r, 6.9314718056e-1f);
    p = fmaf(p, r, 1.0f);
    return __int_as_float(__float_as_int(p) + (n << 23));
}

__device__ __forceinline__ void split_pack(float x, float y, uint32_t& hi, uint32_t& lo) {
    __nv_bfloat162 h = __float22bfloat162_rn(make_float2(x, y));
    float2 hb = __bfloat1622float2(h);
    __nv_bfloat162 l = __float22bfloat162_rn(make_float2(x - hb.x, y - hb.y));
    hi = *(uint32_t*)&h;
    lo = *(uint32_t*)&l;
}

// ---------------------------------------------------------------------------
// Split fp32 -> (bf16 hi, bf16 lo). Vectorized by 4.
// ---------------------------------------------------------------------------
__global__ void split_kernel(const float* __restrict__ in,
                             __nv_bfloat16* __restrict__ hi,
                             __nv_bfloat16* __restrict__ lo, int n4)
{
    int i = blockIdx.x * blockDim.x + threadIdx.x;
    if (i >= n4) return;
    float4 v = ((const float4*)in)[i];
    uint32_t h0, l0, h1, l1;
    split_pack(v.x, v.y, h0, l0);
    split_pack(v.z, v.w, h1, l1);
    ((uint32_t*)hi)[2 * i]     = h0;
    ((uint32_t*)hi)[2 * i + 1] = h1;
    ((uint32_t*)lo)[2 * i]     = l0;
    ((uint32_t*)lo)[2 * i + 1] = l1;
}

// All 4 weights in one launch (blockIdx.y selects the weight)
__global__ void split4_kernel(const float* __restrict__ w0, const float* __restrict__ w1,
                              const float* __restrict__ w2, const float* __restrict__ w3,
                              __nv_bfloat16* __restrict__ h0, __nv_bfloat16* __restrict__ l0,
                              __nv_bfloat16* __restrict__ h1, __nv_bfloat16* __restrict__ l1,
                              __nv_bfloat16* __restrict__ h2, __nv_bfloat16* __restrict__ l2,
                              __nv_bfloat16* __restrict__ h3, __nv_bfloat16* __restrict__ l3,
                              int n4)
{
    int i = blockIdx.x * blockDim.x + threadIdx.x;
    if (i >= n4) return;
    const float* in; __nv_bfloat16 *hi, *lo;
    switch (blockIdx.y) {
        case 0: in = w0; hi = h0; lo = l0; break;
        case 1: in = w1; hi = h1; lo = l1; break;
        case 2: in = w2; hi = h2; lo = l2; break;
        default: in = w3; hi = h3; lo = l3; break;
    }
    float4 v = ((const float4*)in)[i];
    uint32_t ha, la, hb, lb;
    split_pack(v.x, v.y, ha, la);
    split_pack(v.z, v.w, hb, lb);
    ((uint32_t*)hi)[2 * i]     = ha;
    ((uint32_t*)hi)[2 * i + 1] = hb;
    ((uint32_t*)lo)[2 * i]     = la;
    ((uint32_t*)lo)[2 * i + 1] = lb;
}

// ---------------------------------------------------------------------------
// GEMM core (R10, measured-best): 2-stage, 2 syncs/iter, BK=64.
// Stage = A(16KB) + B(16KB); 2 stages = 64KB dynamic smem, 2 CTAs/SM.
// Block 128x128, 256 threads (8 warps = 4M x 2N).
// ---------------------------------------------------------------------------
#define GBM 128
#define GBN 128
#define GBK 64
#define GSTAGE 32768
#define GEMM_SMEM (2 * GSTAGE)
__device__ __forceinline__ uint32_t swg(int r, int c) {
    return (uint32_t)(r * 128 + ((c ^ (r & 7)) << 4));
}

__device__ __forceinline__ void gemm_core(
    const __nv_bfloat16* __restrict__ Ahi, const __nv_bfloat16* __restrict__ Alo,
    const __nv_bfloat16* __restrict__ Bhi, const __nv_bfloat16* __restrict__ Blo,
    int bm, int bn, int K, char* sm, float acc[2][8][4])
{
    const int tid  = threadIdx.x;
    const int wid  = tid >> 5;
    const int lane = tid & 31;
    const int mbase = (wid & 3) * 32;
    const int nbase = (wid >> 2) * 64;

    const uint32_t sBase = smem_u32(sm);

    const __nv_bfloat16* Asegs[3] = {Ahi, Alo, Ahi};
    const __nv_bfloat16* Bsegs[3] = {Bhi, Bhi, Blo};

    const int KIT = K / GBK;          // 32
    const int NIT = 3 * KIT;          // 96

    auto issue = [&](int it, int buf) {
        const uint32_t st = sBase + (uint32_t)buf * GSTAGE;
        const int seg = it / KIT;
        const int k0  = (it % KIT) * GBK;
        const __nv_bfloat16* A  = Asegs[seg];
        const __nv_bfloat16* Bp = Bsegs[seg];
#pragma unroll
        for (int i = 0; i < 4; i++) {
            int id = i * 256 + tid;
            int r = id >> 3, c = id & 7;
            uint32_t off = swg(r, c);
            cp_async16(st + off,         A  + (size_t)(bm + r) * K + k0 + c * 8);
            cp_async16(st + 16384 + off, Bp + (size_t)(bn + r) * K + k0 + c * 8);
        }
        CP_COMMIT();
    };

#pragma unroll
    for (int mt = 0; mt < 2; mt++)
#pragma unroll
        for (int nt = 0; nt < 8; nt++)
#pragma unroll
            for (int e = 0; e < 4; e++) acc[mt][nt][e] = 0.f;

    issue(0, 0);

    for (int it = 0; it < NIT; it++) {
        const int buf = it & 1;
        if (it + 1 < NIT) {
            issue(it + 1, buf ^ 1);
            CP_WAIT(1);
        } else {
            CP_WAIT(0);
        }
        __syncthreads();

        const uint32_t sA = sBase + (uint32_t)buf * GSTAGE;
        const uint32_t sB = sA + 16384;

#pragma unroll
        for (int ks = 0; ks < 4; ks++) {
            uint32_t afr[2][4];
#pragma unroll
            for (int mt = 0; mt < 2; mt++) {
                int row   = mbase + mt * 16 + (lane & 15);
                int chunk = ks * 2 + (lane >> 4);
                ldmatrix_x4(afr[mt][0], afr[mt][1], afr[mt][2], afr[mt][3],
                            sA + swg(row, chunk));
            }
            uint32_t bfr[8][2];
#pragma unroll
            for (int nt2 = 0; nt2 < 4; nt2++) {
                int row   = nbase + nt2 * 16 + ((lane >> 4) << 3) + (lane & 7);
                int chunk = ks * 2 + ((lane >> 3) & 1);
                ldmatrix_x4(bfr[nt2 * 2][0], bfr[nt2 * 2][1],
                            bfr[nt2 * 2 + 1][0], bfr[nt2 * 2 + 1][1],
                            sB + swg(row, chunk));
            }
#pragma unroll
            for (int mt = 0; mt < 2; mt++)
#pragma unroll
                for (int nt = 0; nt < 8; nt++)
                    mma_bf16(acc[mt][nt], afr[mt], bfr[nt]);
        }
        __syncthreads();
    }
}

// ---------------------------------------------------------------------------
// Fused QKV GEMM: blockIdx.z selects {Wq(rope), Wk(rope), Wv(plain)}.
// ---------------------------------------------------------------------------
__global__ __launch_bounds__(256, 2) void qkv_gemm(
    const __nv_bfloat16* __restrict__ xhi, const __nv_bfloat16* __restrict__ xlo,
    const __nv_bfloat16* __restrict__ wqh, const __nv_bfloat16* __restrict__ wql,
    const __nv_bfloat16* __restrict__ wkh, const __nv_bfloat16* __restrict__ wkl,
    const __nv_bfloat16* __restrict__ wvh, const __nv_bfloat16* __restrict__ wvl,
    __nv_bfloat16* __restrict__ qhi, __nv_bfloat16* __restrict__ qlo,
    __nv_bfloat16* __restrict__ khi, __nv_bfloat16* __restrict__ klo,
    __nv_bfloat16* __restrict__ vhi, __nv_bfloat16* __restrict__ vlo,
    const float* __restrict__ cosb, const float* __restrict__ sinb)
{
    extern __shared__ __align__(1024) char smq[];

    const int bm = blockIdx.y * GBM;
    const int bn = blockIdx.x * GBN;
    const int z  = blockIdx.z;

    const __nv_bfloat16 *Bh, *Bl;
    __nv_bfloat16 *Ch, *Cl;
    if (z == 0)      { Bh = wqh; Bl = wql; Ch = qhi; Cl = qlo; }
    else if (z == 1) { Bh = wkh; Bl = wkl; Ch = khi; Cl = klo; }
    else             { Bh = wvh; Bl = wvl; Ch = vhi; Cl = vlo; }
    const bool dorope = (z < 2);

    float acc[2][8][4];
    gemm_core(xhi, xlo, Bh, Bl, bm, bn, DIM_, smq, acc);

    const int lane = threadIdx.x & 31;
    const int wid  = threadIdx.x >> 5;
    const int mbase = (wid & 3) * 32;
    const int nbase = (wid >> 2) * 64;
    const int erow = lane >> 2;
    const int ecol = (lane & 3) * 2;
#pragma unroll
    for (int mt = 0; mt < 2; mt++) {
#pragma unroll
        for (int nt = 0; nt < 8; nt++) {
            const int grow = bm + mbase + mt * 16 + erow;
            const int gcol = bn + nbase + nt * 8 + ecol;
            float v0 = acc[mt][nt][0], v1 = acc[mt][nt][1];
            float v2 = acc[mt][nt][2], v3 = acc[mt][nt][3];
            if (dorope) {
                const int fi = (gcol & 127) >> 1;
                const int s0 = grow & (S_ - 1);
                const int s1 = (grow + 8) & (S_ - 1);
                float c0 = cosb[s0 * 64 + fi], n0 = sinb[s0 * 64 + fi];
                float c1 = cosb[s1 * 64 + fi], n1 = sinb[s1 * 64 + fi];
                float r0 = v0 * c0 - v1 * n0, i0 = v0 * n0 + v1 * c0;
                float r1 = v2 * c1 - v3 * n1, i1 = v2 * n1 + v3 * c1;
                v0 = r0; v1 = i0; v2 = r1; v3 = i1;
            }
            uint32_t h, l;
            size_t o0 = (size_t)grow * DIM_ + gcol;
            size_t o1 = o0 + (size_t)8 * DIM_;
            split_pack(v0, v1, h, l);
            *(uint32_t*)(Ch + o0) = h; *(uint32_t*)(Cl + o0) = l;
            split_pack(v2, v3, h, l);
            *(uint32_t*)(Ch + o1) = h; *(uint32_t*)(Cl + o1) = l;
        }
    }
}

// Output projection GEMM (fp32 out)
__global__ __launch_bounds__(256, 2) void out_gemm(
    const __nv_bfloat16* __restrict__ Ahi, const __nv_bfloat16* __restrict__ Alo,
    const __nv_bfloat16* __restrict__ Bhi, const __nv_bfloat16* __restrict__ Blo,
    float* __restrict__ C)
{
    extern __shared__ __align__(1024) char smo[];
    const int bm = blockIdx.y * GBM;
    const int bn = blockIdx.x * GBN;

    float acc[2][8][4];
    gemm_core(Ahi, Alo, Bhi, Blo, bm, bn, DIM_, smo, acc);

    const int lane = threadIdx.x & 31;
    const int wid  = threadIdx.x >> 5;
    const int mbase = (wid & 3) * 32;
    const int nbase = (wid >> 2) * 64;
    const int erow = lane >> 2;
    const int ecol = (lane & 3) * 2;
#pragma unroll
    for (int mt = 0; mt < 2; mt++) {
#pragma unroll
        for (int nt = 0; nt < 8; nt++) {
            const int grow = bm + mbase + mt * 16 + erow;
            const int gcol = bn + nbase + nt * 8 + ecol;
            float* cp0 = C + (size_t)grow * DIM_ + gcol;
            *(float2*)cp0              = make_float2(acc[mt][nt][0], acc[mt][nt][1]);
            *(float2*)(cp0 + 8 * DIM_) = make_float2(acc[mt][nt][2], acc[mt][nt][3]);
        }
    }
}

// ---------------------------------------------------------------------------
// Flash attention: FA2 on tensor cores, bf16x3. R10 structure +
// CONDITIONAL O-rescale (skips 128 FMA/thread/tile when running max unchanged;
// exact numerics: alpha==1.0f exactly when max doesn't increase).
// CTA: 64 q-rows, 4 warps, kv tiles of 32 rows, double-buffered, 2 CTAs/SM.
// ---------------------------------------------------------------------------
#define FL_SMEM 98304

__device__ __forceinline__ uint32_t fl_off(int r, int c) {
    return (uint32_t)(r * 256 + ((c ^ (r & 7)) << 4));
}

__global__ __launch_bounds__(128, 2) void flash_mma(
    const __nv_bfloat16* __restrict__ qhi, const __nv_bfloat16* __restrict__ qlo,
    const __nv_bfloat16* __restrict__ khi, const __nv_bfloat16* __restrict__ klo,
    const __nv_bfloat16* __restrict__ vhi, const __nv_bfloat16* __restrict__ vlo,
    __nv_bfloat16* __restrict__ othi, __nv_bfloat16* __restrict__ otlo)
{
    extern __shared__ __align__(1024) char sm8[];
    const uint32_t sQh = smem_u32(sm8);
    const uint32_t sQl = sQh + 16384;

    const int qb = (int)gridDim.x - 1 - blockIdx.x;   // largest first
    const int h = blockIdx.y, b = blockIdx.z;
    const int qbase = qb * 64;
    const int tid = threadIdx.x, wid = tid >> 5, lane = tid & 31;
    const int mbase = wid * 16;
    const int colbase = h * DH_;
    const size_t rowg0 = ((size_t)b * S_ + qbase) * DIM_ + colbase;

#pragma unroll
    for (int i = 0; i < 8; i++) {
        int idx = i * 128 + tid;
        int r = idx >> 4, c = idx & 15;
        uint32_t off = fl_off(r, c);
        size_t g = rowg0 + (size_t)r * DIM_ + c * 8;
        cp_async16(sQh + off, qhi + g);
        cp_async16(sQl + off, qlo + g);
    }
    CP_COMMIT();

    const int NT = 2 * qb + 2;

    auto issueKV = [&](int kb, int st) {
        const uint32_t base = sQh + 32768 + st * 32768;
        const size_t krow0 = ((size_t)b * S_ + kb * 32) * DIM_ + colbase;
#pragma unroll
        for (int i = 0; i < 4; i++) {
            int idx = i * 128 + tid;
            int r = idx >> 4, c = idx & 15;
            uint32_t off = fl_off(r, c);
            size_t g = krow0 + (size_t)r * DIM_ + c * 8;
            cp_async16(base + off,          khi + g);
            cp_async16(base + 8192 + off,   klo + g);
            cp_async16(base + 16384 + off,  vhi + g);
            cp_async16(base + 24576 + off,  vlo + g);
        }
        CP_COMMIT();
    };

    issueKV(0, 0);

    float m0 = -1e30f, m1 = -1e30f, l0 = 0.f, l1 = 0.f;
    float o[16][4];
#pragma unroll
    for (int nt = 0; nt < 16; nt++)
#pragma unroll
        for (int e = 0; e < 4; e++) o[nt][e] = 0.f;

    const int rA = lane >> 2;
    const int cq = (lane & 3) * 2;
    const float KARG = 0.1275166782f;

    const int a_r  = (lane & 7) + ((lane >> 3) & 1) * 8;
    const int a_cb = lane >> 4;
    const int bk_r = (lane & 7);
    const int bk_np = lane >> 4;
    const int bk_cb = (lane >> 3) & 1;

    for (int kb = 0; kb < NT; kb++) {
        const int st = kb & 1;
        const uint32_t sKh = sQh + 32768 + st * 32768;
        const uint32_t sKl = sKh + 8192;
        const uint32_t sVh = sKh + 16384;
        const uint32_t sVl = sKh + 24576;

        __syncthreads();
        if (kb + 1 < NT) {
            issueKV(kb + 1, st ^ 1);
            CP_WAIT(1);
        } else {
            CP_WAIT(0);
        }
        __syncthreads();

        const bool active = (kb * 32) <= (qbase + mbase + 15);
        if (active) {
            float sacc[4][4];
#pragma unroll
            for (int nt = 0; nt < 4; nt++)
#pragma unroll
                for (int e = 0; e < 4; e++) sacc[nt][e] = 0.f;

#pragma unroll
            for (int kk = 0; kk < 8; kk++) {
                uint32_t aq[4], aql[4], bk[4][2];
                int arow = mbase + a_r;
                int achk = 2 * kk + a_cb;
                ldmatrix_x4(aq[0], aq[1], aq[2], aq[3], sQh + fl_off(arow, achk));
                ldmatrix_x4(aql[0], aql[1], aql[2], aql[3], sQl + fl_off(arow, achk));
#pragma unroll
                for (int np = 0; np < 2; np++) {
                    int brow = (2 * np + bk_np) * 8 + bk_r;
                    int bchk = 2 * kk + bk_cb;
                    ldmatrix_x4(bk[2 * np][0], bk[2 * np][1],
                                bk[2 * np + 1][0], bk[2 * np + 1][1],
                                sKh + fl_off(brow, bchk));
                }
#pragma unroll
                for (int nt = 0; nt < 4; nt++) mma_bf16(sacc[nt], aq,  bk[nt]);
#pragma unroll
                for (int nt = 0; nt < 4; nt++) mma_bf16(sacc[nt], aql, bk[nt]);
#pragma unroll
                for (int np = 0; np < 2; np++) {
                    int brow = (2 * np + bk_np) * 8 + bk_r;
                    int bchk = 2 * kk + bk_cb;
                    ldmatrix_x4(bk[2 * np][0], bk[2 * np][1],
                                bk[2 * np + 1][0], bk[2 * np + 1][1],
                                sKl + fl_off(brow, bchk));
                }
#pragma unroll
                for (int nt = 0; nt < 4; nt++) mma_bf16(sacc[nt], aq, bk[nt]);
            }

            if (kb * 32 + 31 > qbase + mbase) {
                int rowA = qbase + mbase + rA, rowB = rowA + 8;
#pragma unroll
                for (int nt = 0; nt < 4; nt++) {
                    int c0 = kb * 32 + nt * 8 + cq;
                    if (c0     > rowA) sacc[nt][0] = -1e30f;
                    if (c0 + 1 > rowA) sacc[nt][1] = -1e30f;
                    if (c0     > rowB) sacc[nt][2] = -1e30f;
                    if (c0 + 1 > rowB) sacc[nt][3] = -1e30f;
                }
            }

            float tmA = -1e30f, tmB = -1e30f;
#pragma unroll
            for (int nt = 0; nt < 4; nt++) {
                tmA = fmaxf(tmA, fmaxf(sacc[nt][0], sacc[nt][1]));
                tmB = fmaxf(tmB, fmaxf(sacc[nt][2], sacc[nt][3]));
            }
            tmA = fmaxf(tmA, __shfl_xor_sync(0xffffffffu, tmA, 1));
            tmA = fmaxf(tmA, __shfl_xor_sync(0xffffffffu, tmA, 2));
            tmB = fmaxf(tmB, __shfl_xor_sync(0xffffffffu, tmB, 1));
            tmB = fmaxf(tmB, __shfl_xor_sync(0xffffffffu, tmB, 2));

            // Conditional rescale: alpha==1 exactly when max unchanged.
            float alpha0 = 1.f, alpha1 = 1.f;
            bool upd0 = (tmA > m0), upd1 = (tmB > m1);
            if (upd0) { alpha0 = fexp2((m0 - tmA) * KARG); m0 = tmA; }
            if (upd1) { alpha1 = fexp2((m1 - tmB) * KARG); m1 = tmB; }

            float rs0 = 0.f, rs1 = 0.f;
#pragma unroll
            for (int nt = 0; nt < 4; nt++) {
                float p0 = fexp2((sacc[nt][0] - m0) * KARG);
                float p1 = fexp2((sacc[nt][1] - m0) * KARG);
                float p2 = fexp2((sacc[nt][2] - m1) * KARG);
                float p3 = fexp2((sacc[nt][3] - m1) * KARG);
                sacc[nt][0] = p0; sacc[nt][1] = p1; sacc[nt][2] = p2; sacc[nt][3] = p3;
                rs0 += p0 + p1; rs1 += p2 + p3;
            }
            rs0 += __shfl_xor_sync(0xffffffffu, rs0, 1);
            rs0 += __shfl_xor_sync(0xffffffffu, rs0, 2);
            rs1 += __shfl_xor_sync(0xffffffffu, rs1, 1);
            rs1 += __shfl_xor_sync(0xffffffffu, rs1, 2);
            l0 = alpha0 * l0 + rs0;
            l1 = alpha1 * l1 + rs1;

            if (upd0 || upd1) {
#pragma unroll
                for (int nt = 0; nt < 16; nt++) {
                    o[nt][0] *= alpha0; o[nt][1] *= alpha0;
                    o[nt][2] *= alpha1; o[nt][3] *= alpha1;
                }
            }

            uint32_t phi[2][4], plo[2][4];
#pragma unroll
            for (int kk2 = 0; kk2 < 2; kk2++) {
                split_pack(sacc[2 * kk2][0],     sacc[2 * kk2][1],     phi[kk2][0], plo[kk2][0]);
                split_pack(sacc[2 * kk2][2],     sacc[2 * kk2][3],     phi[kk2][1], plo[kk2][1]);
                split_pack(sacc[2 * kk2 + 1][0], sacc[2 * kk2 + 1][1], phi[kk2][2], plo[kk2][2]);
                split_pack(sacc[2 * kk2 + 1][2], sacc[2 * kk2 + 1][3], phi[kk2][3], plo[kk2][3]);
            }

#pragma unroll
            for (int kk2 = 0; kk2 < 2; kk2++) {
#pragma unroll
                for (int np = 0; np < 8; np++) {
                    uint32_t bv[4];
                    int vrow = kk2 * 16 + a_r;
                    int vchk = 2 * np + a_cb;
                    ldmatrix_x4_trans(bv[0], bv[1], bv[2], bv[3], sVh + fl_off(vrow, vchk));
                    mma_bf16(o[2 * np],     phi[kk2], bv + 0);
                    mma_bf16(o[2 * np + 1], phi[kk2], bv + 2);
                    mma_bf16(o[2 * np],     plo[kk2], bv + 0);
                    mma_bf16(o[2 * np + 1], plo[kk2], bv + 2);
                    ldmatrix_x4_trans(bv[0], bv[1], bv[2], bv[3], sVl + fl_off(vrow, vchk));
                    mma_bf16(o[2 * np],     phi[kk2], bv + 0);
                    mma_bf16(o[2 * np + 1], phi[kk2], bv + 2);
                }
            }
        }
    }

    const float inv0 = 1.f / l0, inv1 = 1.f / l1;
    const int s0 = qbase + mbase + rA;
    const int s1 = s0 + 8;
#pragma unroll
    for (int nt = 0; nt < 16; nt++) {
        int col = colbase + nt * 8 + cq;
        size_t i00 = ((size_t)b * DIM_ + col) * S_;
        size_t i01 = i00 + S_;
        float v00 = o[nt][0] * inv0, v01 = o[nt][1] * inv0;
        float v10 = o[nt][2] * inv1, v11 = o[nt][3] * inv1;
        __nv_bfloat16 hh, ll;
        hh = __float2bfloat16(v00); ll = __float2bfloat16(v00 - __bfloat162float(hh));
        othi[i00 + s0] = hh; otlo[i00 + s0] = ll;
        hh = __float2bfloat16(v01); ll = __float2bfloat16(v01 - __bfloat162float(hh));
        othi[i01 + s0] = hh; otlo[i01 + s0] = ll;
        hh = __float2bfloat16(v10); ll = __float2bfloat16(v10 - __bfloat162float(hh));
        othi[i00 + s1] = hh; otlo[i00 + s1] = ll;
        hh = __float2bfloat16(v11); ll = __float2bfloat16(v11 - __bfloat162float(hh));
        othi[i01 + s1] = hh; otlo[i01 + s1] = ll;
    }
}

// ---------------------------------------------------------------------------
// Launch
// ---------------------------------------------------------------------------
extern "C" void kernel_launch(void* const* d_in, const int* in_sizes, int n_in,
                              void* d_out, int out_size)
{
    const float* x    = (const float*)d_in[0];
    const float* Wq   = (const float*)d_in[1];
    const float* Wk   = (const float*)d_in[2];
    const float* Wv   = (const float*)d_in[3];
    const float* Wo   = (const float*)d_in[4];
    const float* cosb = (const float*)d_in[5];
    const float* sinb = (const float*)d_in[6];
    // d_in[7] = mask: causal handled analytically

    __nv_bfloat16 *xhi, *xlo, *wqhi, *wqlo, *wkhi, *wklo, *wvhi, *wvlo, *wohi, *wolo;
    __nv_bfloat16 *qhi, *qlo, *khi, *klo, *vhi, *vlo, *othi, *otlo;
    cudaGetSymbolAddress((void**)&xhi,  g_xhi);
    cudaGetSymbolAddress((void**)&xlo,  g_xlo);
    cudaGetSymbolAddress((void**)&wqhi, g_wqhi);
    cudaGetSymbolAddress((void**)&wqlo, g_wqlo);
    cudaGetSymbolAddress((void**)&wkhi, g_wkhi);
    cudaGetSymbolAddress((void**)&wklo, g_wklo);
    cudaGetSymbolAddress((void**)&wvhi, g_wvhi);
    cudaGetSymbolAddress((void**)&wvlo, g_wvlo);
    cudaGetSymbolAddress((void**)&wohi, g_wohi);
    cudaGetSymbolAddress((void**)&wolo, g_wolo);
    cudaGetSymbolAddress((void**)&qhi,  g_qhi);
    cudaGetSymbolAddress((void**)&qlo,  g_qlo);
    cudaGetSymbolAddress((void**)&khi,  g_khi);
    cudaGetSymbolAddress((void**)&klo,  g_klo);
    cudaGetSymbolAddress((void**)&vhi,  g_vhi);
    cudaGetSymbolAddress((void**)&vlo,  g_vlo);
    cudaGetSymbolAddress((void**)&othi, g_othi);
    cudaGetSymbolAddress((void**)&otlo, g_otlo);

    cudaFuncSetAttribute(flash_mma, cudaFuncAttributeMaxDynamicSharedMemorySize, FL_SMEM);
    cudaFuncSetAttribute(qkv_gemm, cudaFuncAttributeMaxDynamicSharedMemorySize, GEMM_SMEM);
    cudaFuncSetAttribute(out_gemm, cudaFuncAttributeMaxDynamicSharedMemorySize, GEMM_SMEM);

    // Split inputs into bf16 hi/lo (x + all 4 weights in 2 launches)
    {
        int n4x = MROWS * DIM_ / 4;
        int n4w = DIM_ * DIM_ / 4;
        split_kernel<<<n4x / 256, 256>>>(x, xhi, xlo, n4x);
        dim3 g4(n4w / 256, 4);
        split4_kernel<<<g4, 256>>>(Wq, Wk, Wv, Wo,
                                   wqhi, wqlo, wkhi, wklo,
                                   wvhi, wvlo, wohi, wolo, n4w);
    }

    // Fused QKV projections (rope+split for q,k; split for v) — one launch
    dim3 gqkv(DIM_ / GBN, MROWS / GBM, 3);   // (16, 32, 3) = 1536 CTAs
    qkv_gemm<<<gqkv, 256, GEMM_SMEM>>>(xhi, xlo,
                                       wqhi, wqlo, wkhi, wklo, wvhi, wvlo,
                                       qhi, qlo, khi, klo, vhi, vlo,
                                       cosb, sinb);

    // Tensor-core causal flash attention -> othi/otlo transposed
    dim3 gflash(S_ / 64, H_, B_);            // (32, 16, 2)
    flash_mma<<<gflash, 128, FL_SMEM>>>(qhi, qlo, khi, klo, vhi, vlo, othi, otlo);

    // Output projection (fp32 out)
    dim3 ggemm(DIM_ / GBN, MROWS / GBM);     // (16, 32)
    out_gemm<<<ggemm, 256, GEMM_SMEM>>>(othi, otlo, wohi, wolo, (float*)d_out);
}

// round 12
// speedup vs baseline: 1.4460x; 1.4460x over previous
#include <cuda_runtime.h>
#include <cuda_fp16.h>
#include <cstdint>
#include <math.h>

// Problem constants
#define B_    2
#define S_    2048
#define DIM_  2048
#define H_    16
#define DH_   128
#define MROWS (B_ * S_)   // 4096

// ---------------------------------------------------------------------------
// Scratch (allocation-free rule: device globals)
// ---------------------------------------------------------------------------
__device__ __half g_xhi [MROWS * DIM_];
__device__ __half g_xlo [MROWS * DIM_];
__device__ __half g_wq  [DIM_ * DIM_];
__device__ __half g_wk  [DIM_ * DIM_];
__device__ __half g_wv  [DIM_ * DIM_];
__device__ __half g_wo  [DIM_ * DIM_];
__device__ __half g_qhi [MROWS * DIM_];
__device__ __half g_qlo [MROWS * DIM_];
__device__ __half g_k   [MROWS * DIM_];
__device__ __half g_v   [MROWS * DIM_];
__device__ __half g_othi[MROWS * DIM_];
__device__ __half g_otlo[MROWS * DIM_];

// ---------------------------------------------------------------------------
// Helpers
// ---------------------------------------------------------------------------
__device__ __forceinline__ uint32_t smem_u32(const void* p) {
    uint32_t a;
    asm("{ .reg .u64 t; cvta.to.shared.u64 t, %1; cvt.u32.u64 %0, t; }" : "=r"(a) : "l"(p));
    return a;
}
__device__ __forceinline__ void cp_async16(uint32_t dst, const void* src) {
    asm volatile("cp.async.cg.shared.global [%0], [%1], 16;" :: "r"(dst), "l"(src));
}
#define CP_COMMIT() asm volatile("cp.async.commit_group;" ::: "memory")
#define CP_WAIT(n)  asm volatile("cp.async.wait_group %0;" :: "n"(n) : "memory")

__device__ __forceinline__ void ldmatrix_x4(uint32_t& r0, uint32_t& r1,
                                            uint32_t& r2, uint32_t& r3, uint32_t addr) {
    asm volatile("ldmatrix.sync.aligned.m8n8.x4.shared.b16 {%0,%1,%2,%3}, [%4];"
                 : "=r"(r0), "=r"(r1), "=r"(r2), "=r"(r3) : "r"(addr));
}
__device__ __forceinline__ void ldmatrix_x4_trans(uint32_t& r0, uint32_t& r1,
                                                  uint32_t& r2, uint32_t& r3, uint32_t addr) {
    asm volatile("ldmatrix.sync.aligned.m8n8.x4.trans.shared.b16 {%0,%1,%2,%3}, [%4];"
                 : "=r"(r0), "=r"(r1), "=r"(r2), "=r"(r3) : "r"(addr));
}
__device__ __forceinline__ void mma_f16(float* c, const uint32_t* a, const uint32_t* b) {
    asm volatile(
        "mma.sync.aligned.m16n8k16.row.col.f32.f16.f16.f32 "
        "{%0,%1,%2,%3}, {%4,%5,%6,%7}, {%8,%9}, {%0,%1,%2,%3};"
        : "+f"(c[0]), "+f"(c[1]), "+f"(c[2]), "+f"(c[3])
        : "r"(a[0]), "r"(a[1]), "r"(a[2]), "r"(a[3]), "r"(b[0]), "r"(b[1]));
}

// Fast exp2 (degree-5 poly on FMA pipe, avoids MUFU bottleneck)
__device__ __forceinline__ float fexp2(float x) {
    x = fmaxf(x, -80.f);
    float f = x + 12582912.f;
    int  n  = __float_as_int(f) - 0x4B400000;
    float r = x - (f - 12582912.f);
    float p =            1.3333558146e-3f;
    p = fmaf(p, r, 9.6181291076e-3f);
    p = fmaf(p, r, 5.5504108665e-2f);
    p = fmaf(p, r, 2.4022650696e-1f);
    p = fmaf(p, r, 6.9314718056e-1f);
    p = fmaf(p, r, 1.0f);
    return __int_as_float(__float_as_int(p) + (n << 23));
}

// fp16 split: x = hi + lo with ~22-bit combined mantissa
__device__ __forceinline__ void split_pack_h(float x, float y, uint32_t& hi, uint32_t& lo) {
    __half2 h = __float22half2_rn(make_float2(x, y));
    float2 hb = __half22float2(h);
    __half2 l = __float22half2_rn(make_float2(x - hb.x, y - hb.y));
    hi = *(uint32_t*)&h;
    lo = *(uint32_t*)&l;
}
__device__ __forceinline__ uint32_t pack_h(float x, float y) {
    __half2 h = __float22half2_rn(make_float2(x, y));
    return *(uint32_t*)&h;
}

// ---------------------------------------------------------------------------
// Split fp32 -> (fp16 hi, fp16 lo). Vectorized by 4.
// ---------------------------------------------------------------------------
__global__ void split_kernel(const float* __restrict__ in,
                             __half* __restrict__ hi,
                             __half* __restrict__ lo, int n4)
{
    int i = blockIdx.x * blockDim.x + threadIdx.x;
    if (i >= n4) return;
    float4 v = ((const float4*)in)[i];
    uint32_t h0, l0, h1, l1;
    split_pack_h(v.x, v.y, h0, l0);
    split_pack_h(v.z, v.w, h1, l1);
    ((uint32_t*)hi)[2 * i]     = h0;
    ((uint32_t*)hi)[2 * i + 1] = h1;
    ((uint32_t*)lo)[2 * i]     = l0;
    ((uint32_t*)lo)[2 * i + 1] = l1;
}

// Convert 4 weights to single fp16 in one launch (blockIdx.y selects)
__global__ void conv4_kernel(const float* __restrict__ w0, const float* __restrict__ w1,
                             const float* __restrict__ w2, const float* __restrict__ w3,
                             __half* __restrict__ h0, __half* __restrict__ h1,
                             __half* __restrict__ h2, __half* __restrict__ h3, int n4)
{
    int i = blockIdx.x * blockDim.x + threadIdx.x;
    if (i >= n4) return;
    const float* in; __half* out;
    switch (blockIdx.y) {
        case 0: in = w0; out = h0; break;
        case 1: in = w1; out = h1; break;
        case 2: in = w2; out = h2; break;
        default: in = w3; out = h3; break;
    }
    float4 v = ((const float4*)in)[i];
    ((uint32_t*)out)[2 * i]     = pack_h(v.x, v.y);
    ((uint32_t*)out)[2 * i + 1] = pack_h(v.z, v.w);
}

// ---------------------------------------------------------------------------
// GEMM core (R10 loop shape): 2-stage, 2 syncs/iter, BK=64, TWO passes:
//   C = Ahi@B^T + Alo@B^T   (B single fp16; dropped term ~2^-12 relative)
// Stage = A(16KB) + B(16KB); 2 stages = 64KB dynamic smem, 2 CTAs/SM.
// Block 128x128, 256 threads (8 warps = 4M x 2N).
// ---------------------------------------------------------------------------
#define GBM 128
#define GBN 128
#define GBK 64
#define GSTAGE 32768
#define GEMM_SMEM (2 * GSTAGE)
__device__ __forceinline__ uint32_t swg(int r, int c) {
    return (uint32_t)(r * 128 + ((c ^ (r & 7)) << 4));
}

__device__ __forceinline__ void gemm_core(
    const __half* __restrict__ Ahi, const __half* __restrict__ Alo,
    const __half* __restrict__ Bs,
    int bm, int bn, int K, char* sm, float acc[2][8][4])
{
    const int tid  = threadIdx.x;
    const int wid  = tid >> 5;
    const int lane = tid & 31;
    const int mbase = (wid & 3) * 32;
    const int nbase = (wid >> 2) * 64;

    const uint32_t sBase = smem_u32(sm);

    const __half* Asegs[2] = {Ahi, Alo};

    const int KIT = K / GBK;          // 32
    const int NIT = 2 * KIT;          // 64

    auto issue = [&](int it, int buf) {
        const uint32_t st = sBase + (uint32_t)buf * GSTAGE;
        const int seg = it / KIT;
        const int k0  = (it % KIT) * GBK;
        const __half* A = Asegs[seg];
#pragma unroll
        for (int i = 0; i < 4; i++) {
            int id = i * 256 + tid;
            int r = id >> 3, c = id & 7;
            uint32_t off = swg(r, c);
            cp_async16(st + off,         A  + (size_t)(bm + r) * K + k0 + c * 8);
            cp_async16(st + 16384 + off, Bs + (size_t)(bn + r) * K + k0 + c * 8);
        }
        CP_COMMIT();
    };

#pragma unroll
    for (int mt = 0; mt < 2; mt++)
#pragma unroll
        for (int nt = 0; nt < 8; nt++)
#pragma unroll
            for (int e = 0; e < 4; e++) acc[mt][nt][e] = 0.f;

    issue(0, 0);

    for (int it = 0; it < NIT; it++) {
        const int buf = it & 1;
        if (it + 1 < NIT) {
            issue(it + 1, buf ^ 1);
            CP_WAIT(1);
        } else {
            CP_WAIT(0);
        }
        __syncthreads();

        const uint32_t sA = sBase + (uint32_t)buf * GSTAGE;
        const uint32_t sB = sA + 16384;

#pragma unroll
        for (int ks = 0; ks < 4; ks++) {
            uint32_t afr[2][4];
#pragma unroll
            for (int mt = 0; mt < 2; mt++) {
                int row   = mbase + mt * 16 + (lane & 15);
                int chunk = ks * 2 + (lane >> 4);
                ldmatrix_x4(afr[mt][0], afr[mt][1], afr[mt][2], afr[mt][3],
                            sA + swg(row, chunk));
            }
            uint32_t bfr[8][2];
#pragma unroll
            for (int nt2 = 0; nt2 < 4; nt2++) {
                int row   = nbase + nt2 * 16 + ((lane >> 4) << 3) + (lane & 7);
                int chunk = ks * 2 + ((lane >> 3) & 1);
                ldmatrix_x4(bfr[nt2 * 2][0], bfr[nt2 * 2][1],
                            bfr[nt2 * 2 + 1][0], bfr[nt2 * 2 + 1][1],
                            sB + swg(row, chunk));
            }
#pragma unroll
            for (int mt = 0; mt < 2; mt++)
#pragma unroll
                for (int nt = 0; nt < 8; nt++)
                    mma_f16(acc[mt][nt], afr[mt], bfr[nt]);
        }
        __syncthreads();
    }
}

// ---------------------------------------------------------------------------
// Fused QKV GEMM: blockIdx.z selects {Wq(rope,split), Wk(rope,single),
//                                     Wv(single)}.
// ---------------------------------------------------------------------------
__global__ __launch_bounds__(256, 2) void qkv_gemm(
    const __half* __restrict__ xhi, const __half* __restrict__ xlo,
    const __half* __restrict__ wq, const __half* __restrict__ wk,
    const __half* __restrict__ wv,
    __half* __restrict__ qhi, __half* __restrict__ qlo,
    __half* __restrict__ kk, __half* __restrict__ vv,
    const float* __restrict__ cosb, const float* __restrict__ sinb)
{
    extern __shared__ __align__(1024) char smq[];

    const int bm = blockIdx.y * GBM;
    const int bn = blockIdx.x * GBN;
    const int z  = blockIdx.z;

    const __half* Bs = (z == 0) ? wq : (z == 1) ? wk : wv;

    float acc[2][8][4];
    gemm_core(xhi, xlo, Bs, bm, bn, DIM_, smq, acc);

    const int lane = threadIdx.x & 31;
    const int wid  = threadIdx.x >> 5;
    const int mbase = (wid & 3) * 32;
    const int nbase = (wid >> 2) * 64;
    const int erow = lane >> 2;
    const int ecol = (lane & 3) * 2;
#pragma unroll
    for (int mt = 0; mt < 2; mt++) {
#pragma unroll
        for (int nt = 0; nt < 8; nt++) {
            const int grow = bm + mbase + mt * 16 + erow;
            const int gcol = bn + nbase + nt * 8 + ecol;
            float v0 = acc[mt][nt][0], v1 = acc[mt][nt][1];
            float v2 = acc[mt][nt][2], v3 = acc[mt][nt][3];
            if (z < 2) {   // RoPE for q and k
                const int fi = (gcol & 127) >> 1;
                const int s0 = grow & (S_ - 1);
                const int s1 = (grow + 8) & (S_ - 1);
                float c0 = cosb[s0 * 64 + fi], n0 = sinb[s0 * 64 + fi];
                float c1 = cosb[s1 * 64 + fi], n1 = sinb[s1 * 64 + fi];
                float r0 = v0 * c0 - v1 * n0, i0 = v0 * n0 + v1 * c0;
                float r1 = v2 * c1 - v3 * n1, i1 = v2 * n1 + v3 * c1;
                v0 = r0; v1 = i0; v2 = r1; v3 = i1;
            }
            size_t o0 = (size_t)grow * DIM_ + gcol;
            size_t o1 = o0 + (size_t)8 * DIM_;
            if (z == 0) {          // Q: split hi/lo
                uint32_t h, l;
                split_pack_h(v0, v1, h, l);
                *(uint32_t*)(qhi + o0) = h; *(uint32_t*)(qlo + o0) = l;
                split_pack_h(v2, v3, h, l);
                *(uint32_t*)(qhi + o1) = h; *(uint32_t*)(qlo + o1) = l;
            } else if (z == 1) {   // K: single fp16
                *(uint32_t*)(kk + o0) = pack_h(v0, v1);
                *(uint32_t*)(kk + o1) = pack_h(v2, v3);
            } else {               // V: single fp16
                *(uint32_t*)(vv + o0) = pack_h(v0, v1);
                *(uint32_t*)(vv + o1) = pack_h(v2, v3);
            }
        }
    }
}

// Output projection GEMM (fp32 out): A = Ot split, B = Wo single
__global__ __launch_bounds__(256, 2) void out_gemm(
    const __half* __restrict__ Ahi, const __half* __restrict__ Alo,
    const __half* __restrict__ Bs, float* __restrict__ C)
{
    extern __shared__ __align__(1024) char smo[];
    const int bm = blockIdx.y * GBM;
    const int bn = blockIdx.x * GBN;

    float acc[2][8][4];
    gemm_core(Ahi, Alo, Bs, bm, bn, DIM_, smo, acc);

    const int lane = threadIdx.x & 31;
    const int wid  = threadIdx.x >> 5;
    const int mbase = (wid & 3) * 32;
    const int nbase = (wid >> 2) * 64;
    const int erow = lane >> 2;
    const int ecol = (lane & 3) * 2;
#pragma unroll
    for (int mt = 0; mt < 2; mt++) {
#pragma unroll
        for (int nt = 0; nt < 8; nt++) {
            const int grow = bm + mbase + mt * 16 + erow;
            const int gcol = bn + nbase + nt * 8 + ecol;
            float* cp0 = C + (size_t)grow * DIM_ + gcol;
            *(float2*)cp0              = make_float2(acc[mt][nt][0], acc[mt][nt][1]);
            *(float2*)(cp0 + 8 * DIM_) = make_float2(acc[mt][nt][2], acc[mt][nt][3]);
        }
    }
}

// ---------------------------------------------------------------------------
// Flash attention: FA2 on tensor cores, fp16 2-pass (Q split; K,V single).
// CTA: 64 q-rows, 4 warps, kv tiles of 32 rows, double-buffered.
// smem: Qhi 16K + Qlo 16K + 2 stages x (K 8K + V 8K) = 64KB, 2 CTAs/SM.
// ---------------------------------------------------------------------------
#define FL_SMEM 65536

__device__ __forceinline__ uint32_t fl_off(int r, int c) {
    return (uint32_t)(r * 256 + ((c ^ (r & 7)) << 4));
}

__global__ __launch_bounds__(128, 2) void flash_mma(
    const __half* __restrict__ qhi, const __half* __restrict__ qlo,
    const __half* __restrict__ kk, const __half* __restrict__ vv,
    __half* __restrict__ othi, __half* __restrict__ otlo)
{
    extern __shared__ __align__(1024) char sm8[];
    const uint32_t sQh = smem_u32(sm8);
    const uint32_t sQl = sQh + 16384;

    const int qb = (int)gridDim.x - 1 - blockIdx.x;   // largest first
    const int h = blockIdx.y, b = blockIdx.z;
    const int qbase = qb * 64;
    const int tid = threadIdx.x, wid = tid >> 5, lane = tid & 31;
    const int mbase = wid * 16;
    const int colbase = h * DH_;
    const size_t rowg0 = ((size_t)b * S_ + qbase) * DIM_ + colbase;

#pragma unroll
    for (int i = 0; i < 8; i++) {
        int idx = i * 128 + tid;
        int r = idx >> 4, c = idx & 15;
        uint32_t off = fl_off(r, c);
        size_t g = rowg0 + (size_t)r * DIM_ + c * 8;
        cp_async16(sQh + off, qhi + g);
        cp_async16(sQl + off, qlo + g);
    }
    CP_COMMIT();

    const int NT = 2 * qb + 2;

    auto issueKV = [&](int kb, int st) {
        const uint32_t base = sQh + 32768 + st * 16384;
        const size_t krow0 = ((size_t)b * S_ + kb * 32) * DIM_ + colbase;
#pragma unroll
        for (int i = 0; i < 4; i++) {
            int idx = i * 128 + tid;
            int r = idx >> 4, c = idx & 15;
            uint32_t off = fl_off(r, c);
            size_t g = krow0 + (size_t)r * DIM_ + c * 8;
            cp_async16(base + off,        kk + g);
            cp_async16(base + 8192 + off, vv + g);
        }
        CP_COMMIT();
    };

    issueKV(0, 0);

    float m0 = -1e30f, m1 = -1e30f, l0 = 0.f, l1 = 0.f;
    float o[16][4];
#pragma unroll
    for (int nt = 0; nt < 16; nt++)
#pragma unroll
        for (int e = 0; e < 4; e++) o[nt][e] = 0.f;

    const int rA = lane >> 2;
    const int cq = (lane & 3) * 2;
    const float KARG = 0.1275166782f;   // (1/sqrt(128)) * log2(e)

    const int a_r  = (lane & 7) + ((lane >> 3) & 1) * 8;
    const int a_cb = lane >> 4;
    const int bk_r = (lane & 7);
    const int bk_np = lane >> 4;
    const int bk_cb = (lane >> 3) & 1;

    for (int kb = 0; kb < NT; kb++) {
        const int st = kb & 1;
        const uint32_t sK = sQh + 32768 + st * 16384;
        const uint32_t sV = sK + 8192;

        __syncthreads();
        if (kb + 1 < NT) {
            issueKV(kb + 1, st ^ 1);
            CP_WAIT(1);
        } else {
            CP_WAIT(0);
        }
        __syncthreads();

        const bool active = (kb * 32) <= (qbase + mbase + 15);
        if (active) {
            // ---- S = Q @ K^T (fp16 2-pass) ----
            float sacc[4][4];
#pragma unroll
            for (int nt = 0; nt < 4; nt++)
#pragma unroll
                for (int e = 0; e < 4; e++) sacc[nt][e] = 0.f;

#pragma unroll
            for (int kkk = 0; kkk < 8; kkk++) {
                uint32_t aq[4], aql[4], bk[4][2];
                int arow = mbase + a_r;
                int achk = 2 * kkk + a_cb;
                ldmatrix_x4(aq[0], aq[1], aq[2], aq[3], sQh + fl_off(arow, achk));
                ldmatrix_x4(aql[0], aql[1], aql[2], aql[3], sQl + fl_off(arow, achk));
#pragma unroll
                for (int np = 0; np < 2; np++) {
                    int brow = (2 * np + bk_np) * 8 + bk_r;
                    int bchk = 2 * kkk + bk_cb;
                    ldmatrix_x4(bk[2 * np][0], bk[2 * np][1],
                                bk[2 * np + 1][0], bk[2 * np + 1][1],
                                sK + fl_off(brow, bchk));
                }
#pragma unroll
                for (int nt = 0; nt < 4; nt++) mma_f16(sacc[nt], aq,  bk[nt]);
#pragma unroll
                for (int nt = 0; nt < 4; nt++) mma_f16(sacc[nt], aql, bk[nt]);
            }

            if (kb * 32 + 31 > qbase + mbase) {
                int rowA = qbase + mbase + rA, rowB = rowA + 8;
#pragma unroll
                for (int nt = 0; nt < 4; nt++) {
                    int c0 = kb * 32 + nt * 8 + cq;
                    if (c0     > rowA) sacc[nt][0] = -1e30f;
                    if (c0 + 1 > rowA) sacc[nt][1] = -1e30f;
                    if (c0     > rowB) sacc[nt][2] = -1e30f;
                    if (c0 + 1 > rowB) sacc[nt][3] = -1e30f;
                }
            }

            float tmA = -1e30f, tmB = -1e30f;
#pragma unroll
            for (int nt = 0; nt < 4; nt++) {
                tmA = fmaxf(tmA, fmaxf(sacc[nt][0], sacc[nt][1]));
                tmB = fmaxf(tmB, fmaxf(sacc[nt][2], sacc[nt][3]));
            }
            tmA = fmaxf(tmA, __shfl_xor_sync(0xffffffffu, tmA, 1));
            tmA = fmaxf(tmA, __shfl_xor_sync(0xffffffffu, tmA, 2));
            tmB = fmaxf(tmB, __shfl_xor_sync(0xffffffffu, tmB, 1));
            tmB = fmaxf(tmB, __shfl_xor_sync(0xffffffffu, tmB, 2));

            float alpha0 = 1.f, alpha1 = 1.f;
            bool upd0 = (tmA > m0), upd1 = (tmB > m1);
            if (upd0) { alpha0 = fexp2((m0 - tmA) * KARG); m0 = tmA; }
            if (upd1) { alpha1 = fexp2((m1 - tmB) * KARG); m1 = tmB; }

            float rs0 = 0.f, rs1 = 0.f;
#pragma unroll
            for (int nt = 0; nt < 4; nt++) {
                float p0 = fexp2((sacc[nt][0] - m0) * KARG);
                float p1 = fexp2((sacc[nt][1] - m0) * KARG);
                float p2 = fexp2((sacc[nt][2] - m1) * KARG);
                float p3 = fexp2((sacc[nt][3] - m1) * KARG);
                sacc[nt][0] = p0; sacc[nt][1] = p1; sacc[nt][2] = p2; sacc[nt][3] = p3;
                rs0 += p0 + p1; rs1 += p2 + p3;
            }
            rs0 += __shfl_xor_sync(0xffffffffu, rs0, 1);
            rs0 += __shfl_xor_sync(0xffffffffu, rs0, 2);
            rs1 += __shfl_xor_sync(0xffffffffu, rs1, 1);
            rs1 += __shfl_xor_sync(0xffffffffu, rs1, 2);
            l0 = alpha0 * l0 + rs0;
            l1 = alpha1 * l1 + rs1;

            if (upd0 || upd1) {
#pragma unroll
                for (int nt = 0; nt < 16; nt++) {
                    o[nt][0] *= alpha0; o[nt][1] *= alpha0;
                    o[nt][2] *= alpha1; o[nt][3] *= alpha1;
                }
            }

            // ---- pack P fragments (fp16 hi/lo) ----
            uint32_t phi[2][4], plo[2][4];
#pragma unroll
            for (int kk2 = 0; kk2 < 2; kk2++) {
                split_pack_h(sacc[2 * kk2][0],     sacc[2 * kk2][1],     phi[kk2][0], plo[kk2][0]);
                split_pack_h(sacc[2 * kk2][2],     sacc[2 * kk2][3],     phi[kk2][1], plo[kk2][1]);
                split_pack_h(sacc[2 * kk2 + 1][0], sacc[2 * kk2 + 1][1], phi[kk2][2], plo[kk2][2]);
                split_pack_h(sacc[2 * kk2 + 1][2], sacc[2 * kk2 + 1][3], phi[kk2][3], plo[kk2][3]);
            }

            // ---- O += P @ V (fp16 2-pass; V single) ----
#pragma unroll
            for (int kk2 = 0; kk2 < 2; kk2++) {
#pragma unroll
                for (int np = 0; np < 8; np++) {
                    uint32_t bv[4];
                    int vrow = kk2 * 16 + a_r;
                    int vchk = 2 * np + a_cb;
                    ldmatrix_x4_trans(bv[0], bv[1], bv[2], bv[3], sV + fl_off(vrow, vchk));
                    mma_f16(o[2 * np],     phi[kk2], bv + 0);
                    mma_f16(o[2 * np + 1], phi[kk2], bv + 2);
                    mma_f16(o[2 * np],     plo[kk2], bv + 0);
                    mma_f16(o[2 * np + 1], plo[kk2], bv + 2);
                }
            }
        }
    }

    // ---- epilogue: Ot[b, colbase+col, s] = o / l, split fp16 hi/lo ----
    const float inv0 = 1.f / l0, inv1 = 1.f / l1;
    const int s0 = qbase + mbase + rA;
    const int s1 = s0 + 8;
#pragma unroll
    for (int nt = 0; nt < 16; nt++) {
        int col = colbase + nt * 8 + cq;
        size_t i00 = ((size_t)b * DIM_ + col) * S_;
        size_t i01 = i00 + S_;
        float v00 = o[nt][0] * inv0, v01 = o[nt][1] * inv0;
        float v10 = o[nt][2] * inv1, v11 = o[nt][3] * inv1;
        __half hh; float hf;
        hh = __float2half_rn(v00); hf = __half2float(hh);
        othi[i00 + s0] = hh; otlo[i00 + s0] = __float2half_rn(v00 - hf);
        hh = __float2half_rn(v01); hf = __half2float(hh);
        othi[i01 + s0] = hh; otlo[i01 + s0] = __float2half_rn(v01 - hf);
        hh = __float2half_rn(v10); hf = __half2float(hh);
        othi[i00 + s1] = hh; otlo[i00 + s1] = __float2half_rn(v10 - hf);
        hh = __float2half_rn(v11); hf = __half2float(hh);
        othi[i01 + s1] = hh; otlo[i01 + s1] = __float2half_rn(v11 - hf);
    }
}

// ---------------------------------------------------------------------------
// Launch
// ---------------------------------------------------------------------------
extern "C" void kernel_launch(void* const* d_in, const int* in_sizes, int n_in,
                              void* d_out, int out_size)
{
    const float* x    = (const float*)d_in[0];
    const float* Wq   = (const float*)d_in[1];
    const float* Wk   = (const float*)d_in[2];
    const float* Wv   = (const float*)d_in[3];
    const float* Wo   = (const float*)d_in[4];
    const float* cosb = (const float*)d_in[5];
    const float* sinb = (const float*)d_in[6];
    // d_in[7] = mask: causal handled analytically

    __half *xhi, *xlo, *wq, *wk, *wv, *wo, *qhi, *qlo, *kp, *vp, *othi, *otlo;
    cudaGetSymbolAddress((void**)&xhi,  g_xhi);
    cudaGetSymbolAddress((void**)&xlo,  g_xlo);
    cudaGetSymbolAddress((void**)&wq,   g_wq);
    cudaGetSymbolAddress((void**)&wk,   g_wk);
    cudaGetSymbolAddress((void**)&wv,   g_wv);
    cudaGetSymbolAddress((void**)&wo,   g_wo);
    cudaGetSymbolAddress((void**)&qhi,  g_qhi);
    cudaGetSymbolAddress((void**)&qlo,  g_qlo);
    cudaGetSymbolAddress((void**)&kp,   g_k);
    cudaGetSymbolAddress((void**)&vp,   g_v);
    cudaGetSymbolAddress((void**)&othi, g_othi);
    cudaGetSymbolAddress((void**)&otlo, g_otlo);

    cudaFuncSetAttribute(flash_mma, cudaFuncAttributeMaxDynamicSharedMemorySize, FL_SMEM);
    cudaFuncSetAttribute(qkv_gemm, cudaFuncAttributeMaxDynamicSharedMemorySize, GEMM_SMEM);
    cudaFuncSetAttribute(out_gemm, cudaFuncAttributeMaxDynamicSharedMemorySize, GEMM_SMEM);

    // Split x into fp16 hi/lo; convert 4 weights to single fp16
    {
        int n4x = MROWS * DIM_ / 4;
        int n4w = DIM_ * DIM_ / 4;
        split_kernel<<<n4x / 256, 256>>>(x, xhi, xlo, n4x);
        dim3 g4(n4w / 256, 4);
        conv4_kernel<<<g4, 256>>>(Wq, Wk, Wv, Wo, wq, wk, wv, wo, n4w);
    }

    // Fused QKV projections — one launch
    dim3 gqkv(DIM_ / GBN, MROWS / GBM, 3);   // (16, 32, 3) = 1536 CTAs
    qkv_gemm<<<gqkv, 256, GEMM_SMEM>>>(xhi, xlo, wq, wk, wv,
                                       qhi, qlo, kp, vp, cosb, sinb);

    // Tensor-core causal flash attention -> othi/otlo transposed
    dim3 gflash(S_ / 64, H_, B_);            // (32, 16, 2)
    flash_mma<<<gflash, 128, FL_SMEM>>>(qhi, qlo, kp, vp, othi, otlo);

    // Output projection (fp32 out)
    dim3 ggemm(DIM_ / GBN, MROWS / GBM);     // (16, 32)
    out_gemm<<<ggemm, 256, GEMM_SMEM>>>(othi, otlo, wo, (float*)d_out);
}

// round 13
// speedup vs baseline: 1.8792x; 1.2996x over previous
#include <cuda_runtime.h>
#include <cuda_fp16.h>
#include <cstdint>
#include <math.h>

// Problem constants
#define B_    2
#define S_    2048
#define DIM_  2048
#define H_    16
#define DH_   128
#define MROWS (B_ * S_)   // 4096

// ---------------------------------------------------------------------------
// Scratch (allocation-free rule: device globals)
// ---------------------------------------------------------------------------
__device__ __half g_xhi [MROWS * DIM_];
__device__ __half g_xlo [MROWS * DIM_];
__device__ __half g_wq  [DIM_ * DIM_];
__device__ __half g_wk  [DIM_ * DIM_];
__device__ __half g_wv  [DIM_ * DIM_];
__device__ __half g_wo  [DIM_ * DIM_];
__device__ __half g_qhi [MROWS * DIM_];
__device__ __half g_qlo [MROWS * DIM_];
__device__ __half g_k   [MROWS * DIM_];
__device__ __half g_v   [MROWS * DIM_];
__device__ __half g_ot  [MROWS * DIM_];

// ---------------------------------------------------------------------------
// Helpers
// ---------------------------------------------------------------------------
__device__ __forceinline__ uint32_t smem_u32(const void* p) {
    uint32_t a;
    asm("{ .reg .u64 t; cvta.to.shared.u64 t, %1; cvt.u32.u64 %0, t; }" : "=r"(a) : "l"(p));
    return a;
}
__device__ __forceinline__ void cp_async16(uint32_t dst, const void* src) {
    asm volatile("cp.async.cg.shared.global [%0], [%1], 16;" :: "r"(dst), "l"(src));
}
#define CP_COMMIT() asm volatile("cp.async.commit_group;" ::: "memory")
#define CP_WAIT(n)  asm volatile("cp.async.wait_group %0;" :: "n"(n) : "memory")

__device__ __forceinline__ void ldmatrix_x4(uint32_t& r0, uint32_t& r1,
                                            uint32_t& r2, uint32_t& r3, uint32_t addr) {
    asm volatile("ldmatrix.sync.aligned.m8n8.x4.shared.b16 {%0,%1,%2,%3}, [%4];"
                 : "=r"(r0), "=r"(r1), "=r"(r2), "=r"(r3) : "r"(addr));
}
__device__ __forceinline__ void ldmatrix_x4_trans(uint32_t& r0, uint32_t& r1,
                                                  uint32_t& r2, uint32_t& r3, uint32_t addr) {
    asm volatile("ldmatrix.sync.aligned.m8n8.x4.trans.shared.b16 {%0,%1,%2,%3}, [%4];"
                 : "=r"(r0), "=r"(r1), "=r"(r2), "=r"(r3) : "r"(addr));
}
__device__ __forceinline__ void mma_f16(float* c, const uint32_t* a, const uint32_t* b) {
    asm volatile(
        "mma.sync.aligned.m16n8k16.row.col.f32.f16.f16.f32 "
        "{%0,%1,%2,%3}, {%4,%5,%6,%7}, {%8,%9}, {%0,%1,%2,%3};"
        : "+f"(c[0]), "+f"(c[1]), "+f"(c[2]), "+f"(c[3])
        : "r"(a[0]), "r"(a[1]), "r"(a[2]), "r"(a[3]), "r"(b[0]), "r"(b[1]));
}

// Fast exp2 (degree-5 poly on FMA pipe, avoids MUFU bottleneck)
__device__ __forceinline__ float fexp2(float x) {
    x = fmaxf(x, -80.f);
    float f = x + 12582912.f;
    int  n  = __float_as_int(f) - 0x4B400000;
    float r = x - (f - 12582912.f);
    float p =            1.3333558146e-3f;
    p = fmaf(p, r, 9.6181291076e-3f);
    p = fmaf(p, r, 5.5504108665e-2f);
    p = fmaf(p, r, 2.4022650696e-1f);
    p = fmaf(p, r, 6.9314718056e-1f);
    p = fmaf(p, r, 1.0f);
    return __int_as_float(__float_as_int(p) + (n << 23));
}

// fp16 split: x = hi + lo with ~22-bit combined mantissa
__device__ __forceinline__ void split_pack_h(float x, float y, uint32_t& hi, uint32_t& lo) {
    __half2 h = __float22half2_rn(make_float2(x, y));
    float2 hb = __half22float2(h);
    __half2 l = __float22half2_rn(make_float2(x - hb.x, y - hb.y));
    hi = *(uint32_t*)&h;
    lo = *(uint32_t*)&l;
}
__device__ __forceinline__ uint32_t pack_h(float x, float y) {
    __half2 h = __float22half2_rn(make_float2(x, y));
    return *(uint32_t*)&h;
}

// ---------------------------------------------------------------------------
// Split fp32 -> (fp16 hi, fp16 lo). Vectorized by 4.
// ---------------------------------------------------------------------------
__global__ void split_kernel(const float* __restrict__ in,
                             __half* __restrict__ hi,
                             __half* __restrict__ lo, int n4)
{
    int i = blockIdx.x * blockDim.x + threadIdx.x;
    if (i >= n4) return;
    float4 v = ((const float4*)in)[i];
    uint32_t h0, l0, h1, l1;
    split_pack_h(v.x, v.y, h0, l0);
    split_pack_h(v.z, v.w, h1, l1);
    ((uint32_t*)hi)[2 * i]     = h0;
    ((uint32_t*)hi)[2 * i + 1] = h1;
    ((uint32_t*)lo)[2 * i]     = l0;
    ((uint32_t*)lo)[2 * i + 1] = l1;
}

// Convert 4 weights to single fp16 in one launch (blockIdx.y selects)
__global__ void conv4_kernel(const float* __restrict__ w0, const float* __restrict__ w1,
                             const float* __restrict__ w2, const float* __restrict__ w3,
                             __half* __restrict__ h0, __half* __restrict__ h1,
                             __half* __restrict__ h2, __half* __restrict__ h3, int n4)
{
    int i = blockIdx.x * blockDim.x + threadIdx.x;
    if (i >= n4) return;
    const float* in; __half* out;
    switch (blockIdx.y) {
        case 0: in = w0; out = h0; break;
        case 1: in = w1; out = h1; break;
        case 2: in = w2; out = h2; break;
        default: in = w3; out = h3; break;
    }
    float4 v = ((const float4*)in)[i];
    ((uint32_t*)out)[2 * i]     = pack_h(v.x, v.y);
    ((uint32_t*)out)[2 * i + 1] = pack_h(v.z, v.w);
}

// ---------------------------------------------------------------------------
// GEMM core: 2-stage, 2 syncs/iter, BK=64, PASSES in {1,2}:
//   PASSES=2: C = Ahi@B^T + Alo@B^T ; PASSES=1: C = Ahi@B^T
// Stage = A(16KB) + B(16KB); 2 stages = 64KB dynamic smem, 2 CTAs/SM.
// Block 128x128, 256 threads (8 warps = 4M x 2N).
// ---------------------------------------------------------------------------
#define GBM 128
#define GBN 128
#define GBK 64
#define GSTAGE 32768
#define GEMM_SMEM (2 * GSTAGE)
__device__ __forceinline__ uint32_t swg(int r, int c) {
    return (uint32_t)(r * 128 + ((c ^ (r & 7)) << 4));
}

template <int PASSES>
__device__ __forceinline__ void gemm_core(
    const __half* __restrict__ Ahi, const __half* __restrict__ Alo,
    const __half* __restrict__ Bs,
    int bm, int bn, int K, char* sm, float acc[2][8][4])
{
    const int tid  = threadIdx.x;
    const int wid  = tid >> 5;
    const int lane = tid & 31;
    const int mbase = (wid & 3) * 32;
    const int nbase = (wid >> 2) * 64;

    const uint32_t sBase = smem_u32(sm);

    const __half* Asegs[2] = {Ahi, Alo};

    const int KIT = K / GBK;          // 32
    const int NIT = PASSES * KIT;

    auto issue = [&](int it, int buf) {
        const uint32_t st = sBase + (uint32_t)buf * GSTAGE;
        const int seg = it / KIT;
        const int k0  = (it % KIT) * GBK;
        const __half* A = Asegs[seg];
#pragma unroll
        for (int i = 0; i < 4; i++) {
            int id = i * 256 + tid;
            int r = id >> 3, c = id & 7;
            uint32_t off = swg(r, c);
            cp_async16(st + off,         A  + (size_t)(bm + r) * K + k0 + c * 8);
            cp_async16(st + 16384 + off, Bs + (size_t)(bn + r) * K + k0 + c * 8);
        }
        CP_COMMIT();
    };

#pragma unroll
    for (int mt = 0; mt < 2; mt++)
#pragma unroll
        for (int nt = 0; nt < 8; nt++)
#pragma unroll
            for (int e = 0; e < 4; e++) acc[mt][nt][e] = 0.f;

    issue(0, 0);

    for (int it = 0; it < NIT; it++) {
        const int buf = it & 1;
        if (it + 1 < NIT) {
            issue(it + 1, buf ^ 1);
            CP_WAIT(1);
        } else {
            CP_WAIT(0);
        }
        __syncthreads();

        const uint32_t sA = sBase + (uint32_t)buf * GSTAGE;
        const uint32_t sB = sA + 16384;

#pragma unroll
        for (int ks = 0; ks < 4; ks++) {
            uint32_t afr[2][4];
#pragma unroll
            for (int mt = 0; mt < 2; mt++) {
                int row   = mbase + mt * 16 + (lane & 15);
                int chunk = ks * 2 + (lane >> 4);
                ldmatrix_x4(afr[mt][0], afr[mt][1], afr[mt][2], afr[mt][3],
                            sA + swg(row, chunk));
            }
            uint32_t bfr[8][2];
#pragma unroll
            for (int nt2 = 0; nt2 < 4; nt2++) {
                int row   = nbase + nt2 * 16 + ((lane >> 4) << 3) + (lane & 7);
                int chunk = ks * 2 + ((lane >> 3) & 1);
                ldmatrix_x4(bfr[nt2 * 2][0], bfr[nt2 * 2][1],
                            bfr[nt2 * 2 + 1][0], bfr[nt2 * 2 + 1][1],
                            sB + swg(row, chunk));
            }
#pragma unroll
            for (int mt = 0; mt < 2; mt++)
#pragma unroll
                for (int nt = 0; nt < 8; nt++)
                    mma_f16(acc[mt][nt], afr[mt], bfr[nt]);
        }
        __syncthreads();
    }
}

// ---------------------------------------------------------------------------
// Fused QKV GEMM: blockIdx.z selects {Wq(rope,split-out, 2-pass),
//                  Wk(rope,single, 2-pass), Wv(single, 1-pass)}.
// ---------------------------------------------------------------------------
__global__ __launch_bounds__(256, 2) void qkv_gemm(
    const __half* __restrict__ xhi, const __half* __restrict__ xlo,
    const __half* __restrict__ wq, const __half* __restrict__ wk,
    const __half* __restrict__ wv,
    __half* __restrict__ qhi, __half* __restrict__ qlo,
    __half* __restrict__ kk, __half* __restrict__ vv,
    const float* __restrict__ cosb, const float* __restrict__ sinb)
{
    extern __shared__ __align__(1024) char smq[];

    const int bm = blockIdx.y * GBM;
    const int bn = blockIdx.x * GBN;
    const int z  = blockIdx.z;

    float acc[2][8][4];
    if (z == 0)      gemm_core<2>(xhi, xlo, wq, bm, bn, DIM_, smq, acc);
    else if (z == 1) gemm_core<2>(xhi, xlo, wk, bm, bn, DIM_, smq, acc);
    else             gemm_core<1>(xhi, xhi, wv, bm, bn, DIM_, smq, acc);

    const int lane = threadIdx.x & 31;
    const int wid  = threadIdx.x >> 5;
    const int mbase = (wid & 3) * 32;
    const int nbase = (wid >> 2) * 64;
    const int erow = lane >> 2;
    const int ecol = (lane & 3) * 2;
#pragma unroll
    for (int mt = 0; mt < 2; mt++) {
#pragma unroll
        for (int nt = 0; nt < 8; nt++) {
            const int grow = bm + mbase + mt * 16 + erow;
            const int gcol = bn + nbase + nt * 8 + ecol;
            float v0 = acc[mt][nt][0], v1 = acc[mt][nt][1];
            float v2 = acc[mt][nt][2], v3 = acc[mt][nt][3];
            if (z < 2) {   // RoPE for q and k
                const int fi = (gcol & 127) >> 1;
                const int s0 = grow & (S_ - 1);
                const int s1 = (grow + 8) & (S_ - 1);
                float c0 = cosb[s0 * 64 + fi], n0 = sinb[s0 * 64 + fi];
                float c1 = cosb[s1 * 64 + fi], n1 = sinb[s1 * 64 + fi];
                float r0 = v0 * c0 - v1 * n0, i0 = v0 * n0 + v1 * c0;
                float r1 = v2 * c1 - v3 * n1, i1 = v2 * n1 + v3 * c1;
                v0 = r0; v1 = i0; v2 = r1; v3 = i1;
            }
            size_t o0 = (size_t)grow * DIM_ + gcol;
            size_t o1 = o0 + (size_t)8 * DIM_;
            if (z == 0) {          // Q: split hi/lo (score path needs accuracy)
                uint32_t h, l;
                split_pack_h(v0, v1, h, l);
                *(uint32_t*)(qhi + o0) = h; *(uint32_t*)(qlo + o0) = l;
                split_pack_h(v2, v3, h, l);
                *(uint32_t*)(qhi + o1) = h; *(uint32_t*)(qlo + o1) = l;
            } else if (z == 1) {   // K: single fp16
                *(uint32_t*)(kk + o0) = pack_h(v0, v1);
                *(uint32_t*)(kk + o1) = pack_h(v2, v3);
            } else {               // V: single fp16
                *(uint32_t*)(vv + o0) = pack_h(v0, v1);
                *(uint32_t*)(vv + o1) = pack_h(v2, v3);
            }
        }
    }
}

// Output projection GEMM (fp32 out): A = Ot single fp16, 1-pass
__global__ __launch_bounds__(256, 2) void out_gemm(
    const __half* __restrict__ As, const __half* __restrict__ Bs,
    float* __restrict__ C)
{
    extern __shared__ __align__(1024) char smo[];
    const int bm = blockIdx.y * GBM;
    const int bn = blockIdx.x * GBN;

    float acc[2][8][4];
    gemm_core<1>(As, As, Bs, bm, bn, DIM_, smo, acc);

    const int lane = threadIdx.x & 31;
    const int wid  = threadIdx.x >> 5;
    const int mbase = (wid & 3) * 32;
    const int nbase = (wid >> 2) * 64;
    const int erow = lane >> 2;
    const int ecol = (lane & 3) * 2;
#pragma unroll
    for (int mt = 0; mt < 2; mt++) {
#pragma unroll
        for (int nt = 0; nt < 8; nt++) {
            const int grow = bm + mbase + mt * 16 + erow;
            const int gcol = bn + nbase + nt * 8 + ecol;
            float* cp0 = C + (size_t)grow * DIM_ + gcol;
            *(float2*)cp0              = make_float2(acc[mt][nt][0], acc[mt][nt][1]);
            *(float2*)(cp0 + 8 * DIM_) = make_float2(acc[mt][nt][2], acc[mt][nt][3]);
        }
    }
}

// ---------------------------------------------------------------------------
// Flash attention: FA2 on tensor cores. QK fp16 2-pass (Q split, K single);
// PV fp16 1-pass (P single, V single). Output Ot single fp16.
// CTA: 64 q-rows, 4 warps, kv tiles of 32 rows, double-buffered.
// smem: Qhi 16K + Qlo 16K + 2 stages x (K 8K + V 8K) = 64KB, 2 CTAs/SM.
// ---------------------------------------------------------------------------
#define FL_SMEM 65536

__device__ __forceinline__ uint32_t fl_off(int r, int c) {
    return (uint32_t)(r * 256 + ((c ^ (r & 7)) << 4));
}

__global__ __launch_bounds__(128, 2) void flash_mma(
    const __half* __restrict__ qhi, const __half* __restrict__ qlo,
    const __half* __restrict__ kk, const __half* __restrict__ vv,
    __half* __restrict__ ot)
{
    extern __shared__ __align__(1024) char sm8[];
    const uint32_t sQh = smem_u32(sm8);
    const uint32_t sQl = sQh + 16384;

    const int qb = (int)gridDim.x - 1 - blockIdx.x;   // largest first
    const int h = blockIdx.y, b = blockIdx.z;
    const int qbase = qb * 64;
    const int tid = threadIdx.x, wid = tid >> 5, lane = tid & 31;
    const int mbase = wid * 16;
    const int colbase = h * DH_;
    const size_t rowg0 = ((size_t)b * S_ + qbase) * DIM_ + colbase;

#pragma unroll
    for (int i = 0; i < 8; i++) {
        int idx = i * 128 + tid;
        int r = idx >> 4, c = idx & 15;
        uint32_t off = fl_off(r, c);
        size_t g = rowg0 + (size_t)r * DIM_ + c * 8;
        cp_async16(sQh + off, qhi + g);
        cp_async16(sQl + off, qlo + g);
    }
    CP_COMMIT();

    const int NT = 2 * qb + 2;

    auto issueKV = [&](int kb, int st) {
        const uint32_t base = sQh + 32768 + st * 16384;
        const size_t krow0 = ((size_t)b * S_ + kb * 32) * DIM_ + colbase;
#pragma unroll
        for (int i = 0; i < 4; i++) {
            int idx = i * 128 + tid;
            int r = idx >> 4, c = idx & 15;
            uint32_t off = fl_off(r, c);
            size_t g = krow0 + (size_t)r * DIM_ + c * 8;
            cp_async16(base + off,        kk + g);
            cp_async16(base + 8192 + off, vv + g);
        }
        CP_COMMIT();
    };

    issueKV(0, 0);

    float m0 = -1e30f, m1 = -1e30f, l0 = 0.f, l1 = 0.f;
    float o[16][4];
#pragma unroll
    for (int nt = 0; nt < 16; nt++)
#pragma unroll
        for (int e = 0; e < 4; e++) o[nt][e] = 0.f;

    const int rA = lane >> 2;
    const int cq = (lane & 3) * 2;
    const float KARG = 0.1275166782f;   // (1/sqrt(128)) * log2(e)

    const int a_r  = (lane & 7) + ((lane >> 3) & 1) * 8;
    const int a_cb = lane >> 4;
    const int bk_r = (lane & 7);
    const int bk_np = lane >> 4;
    const int bk_cb = (lane >> 3) & 1;

    for (int kb = 0; kb < NT; kb++) {
        const int st = kb & 1;
        const uint32_t sK = sQh + 32768 + st * 16384;
        const uint32_t sV = sK + 8192;

        __syncthreads();
        if (kb + 1 < NT) {
            issueKV(kb + 1, st ^ 1);
            CP_WAIT(1);
        } else {
            CP_WAIT(0);
        }
        __syncthreads();

        const bool active = (kb * 32) <= (qbase + mbase + 15);
        if (active) {
            // ---- S = Q @ K^T (Q split 2-pass, K single) ----
            float sacc[4][4];
#pragma unroll
            for (int nt = 0; nt < 4; nt++)
#pragma unroll
                for (int e = 0; e < 4; e++) sacc[nt][e] = 0.f;

#pragma unroll
            for (int kkk = 0; kkk < 8; kkk++) {
                uint32_t aq[4], aql[4], bk[4][2];
                int arow = mbase + a_r;
                int achk = 2 * kkk + a_cb;
                ldmatrix_x4(aq[0], aq[1], aq[2], aq[3], sQh + fl_off(arow, achk));
                ldmatrix_x4(aql[0], aql[1], aql[2], aql[3], sQl + fl_off(arow, achk));
#pragma unroll
                for (int np = 0; np < 2; np++) {
                    int brow = (2 * np + bk_np) * 8 + bk_r;
                    int bchk = 2 * kkk + bk_cb;
                    ldmatrix_x4(bk[2 * np][0], bk[2 * np][1],
                                bk[2 * np + 1][0], bk[2 * np + 1][1],
                                sK + fl_off(brow, bchk));
                }
#pragma unroll
                for (int nt = 0; nt < 4; nt++) mma_f16(sacc[nt], aq,  bk[nt]);
#pragma unroll
                for (int nt = 0; nt < 4; nt++) mma_f16(sacc[nt], aql, bk[nt]);
            }

            if (kb * 32 + 31 > qbase + mbase) {
                int rowA = qbase + mbase + rA, rowB = rowA + 8;
#pragma unroll
                for (int nt = 0; nt < 4; nt++) {
                    int c0 = kb * 32 + nt * 8 + cq;
                    if (c0     > rowA) sacc[nt][0] = -1e30f;
                    if (c0 + 1 > rowA) sacc[nt][1] = -1e30f;
                    if (c0     > rowB) sacc[nt][2] = -1e30f;
                    if (c0 + 1 > rowB) sacc[nt][3] = -1e30f;
                }
            }

            float tmA = -1e30f, tmB = -1e30f;
#pragma unroll
            for (int nt = 0; nt < 4; nt++) {
                tmA = fmaxf(tmA, fmaxf(sacc[nt][0], sacc[nt][1]));
                tmB = fmaxf(tmB, fmaxf(sacc[nt][2], sacc[nt][3]));
            }
            tmA = fmaxf(tmA, __shfl_xor_sync(0xffffffffu, tmA, 1));
            tmA = fmaxf(tmA, __shfl_xor_sync(0xffffffffu, tmA, 2));
            tmB = fmaxf(tmB, __shfl_xor_sync(0xffffffffu, tmB, 1));
            tmB = fmaxf(tmB, __shfl_xor_sync(0xffffffffu, tmB, 2));

            float alpha0 = 1.f, alpha1 = 1.f;
            bool upd0 = (tmA > m0), upd1 = (tmB > m1);
            if (upd0) { alpha0 = fexp2((m0 - tmA) * KARG); m0 = tmA; }
            if (upd1) { alpha1 = fexp2((m1 - tmB) * KARG); m1 = tmB; }

            float rs0 = 0.f, rs1 = 0.f;
#pragma unroll
            for (int nt = 0; nt < 4; nt++) {
                float p0 = fexp2((sacc[nt][0] - m0) * KARG);
                float p1 = fexp2((sacc[nt][1] - m0) * KARG);
                float p2 = fexp2((sacc[nt][2] - m1) * KARG);
                float p3 = fexp2((sacc[nt][3] - m1) * KARG);
                sacc[nt][0] = p0; sacc[nt][1] = p1; sacc[nt][2] = p2; sacc[nt][3] = p3;
                rs0 += p0 + p1; rs1 += p2 + p3;
            }
            rs0 += __shfl_xor_sync(0xffffffffu, rs0, 1);
            rs0 += __shfl_xor_sync(0xffffffffu, rs0, 2);
            rs1 += __shfl_xor_sync(0xffffffffu, rs1, 1);
            rs1 += __shfl_xor_sync(0xffffffffu, rs1, 2);
            l0 = alpha0 * l0 + rs0;
            l1 = alpha1 * l1 + rs1;

            if (upd0 || upd1) {
#pragma unroll
                for (int nt = 0; nt < 16; nt++) {
                    o[nt][0] *= alpha0; o[nt][1] *= alpha0;
                    o[nt][2] *= alpha1; o[nt][3] *= alpha1;
                }
            }

            // ---- pack P (single fp16) ----
            uint32_t phi[2][4];
#pragma unroll
            for (int kk2 = 0; kk2 < 2; kk2++) {
                phi[kk2][0] = pack_h(sacc[2 * kk2][0],     sacc[2 * kk2][1]);
                phi[kk2][1] = pack_h(sacc[2 * kk2][2],     sacc[2 * kk2][3]);
                phi[kk2][2] = pack_h(sacc[2 * kk2 + 1][0], sacc[2 * kk2 + 1][1]);
                phi[kk2][3] = pack_h(sacc[2 * kk2 + 1][2], sacc[2 * kk2 + 1][3]);
            }

            // ---- O += P @ V (single-pass) ----
#pragma unroll
            for (int kk2 = 0; kk2 < 2; kk2++) {
#pragma unroll
                for (int np = 0; np < 8; np++) {
                    uint32_t bv[4];
                    int vrow = kk2 * 16 + a_r;
                    int vchk = 2 * np + a_cb;
                    ldmatrix_x4_trans(bv[0], bv[1], bv[2], bv[3], sV + fl_off(vrow, vchk));
                    mma_f16(o[2 * np],     phi[kk2], bv + 0);
                    mma_f16(o[2 * np + 1], phi[kk2], bv + 2);
                }
            }
        }
    }

    // ---- epilogue: Ot[b, colbase+col, s] = o / l, single fp16 ----
    const float inv0 = 1.f / l0, inv1 = 1.f / l1;
    const int s0 = qbase + mbase + rA;
    const int s1 = s0 + 8;
#pragma unroll
    for (int nt = 0; nt < 16; nt++) {
        int col = colbase + nt * 8 + cq;
        size_t i00 = ((size_t)b * DIM_ + col) * S_;
        size_t i01 = i00 + S_;
        ot[i00 + s0] = __float2half_rn(o[nt][0] * inv0);
        ot[i01 + s0] = __float2half_rn(o[nt][1] * inv0);
        ot[i00 + s1] = __float2half_rn(o[nt][2] * inv1);
        ot[i01 + s1] = __float2half_rn(o[nt][3] * inv1);
    }
}

// ---------------------------------------------------------------------------
// Launch
// ---------------------------------------------------------------------------
extern "C" void kernel_launch(void* const* d_in, const int* in_sizes, int n_in,
                              void* d_out, int out_size)
{
    const float* x    = (const float*)d_in[0];
    const float* Wq   = (const float*)d_in[1];
    const float* Wk   = (const float*)d_in[2];
    const float* Wv   = (const float*)d_in[3];
    const float* Wo   = (const float*)d_in[4];
    const float* cosb = (const float*)d_in[5];
    const float* sinb = (const float*)d_in[6];
    // d_in[7] = mask: causal handled analytically

    __half *xhi, *xlo, *wq, *wk, *wv, *wo, *qhi, *qlo, *kp, *vp, *ot;
    cudaGetSymbolAddress((void**)&xhi, g_xhi);
    cudaGetSymbolAddress((void**)&xlo, g_xlo);
    cudaGetSymbolAddress((void**)&wq,  g_wq);
    cudaGetSymbolAddress((void**)&wk,  g_wk);
    cudaGetSymbolAddress((void**)&wv,  g_wv);
    cudaGetSymbolAddress((void**)&wo,  g_wo);
    cudaGetSymbolAddress((void**)&qhi, g_qhi);
    cudaGetSymbolAddress((void**)&qlo, g_qlo);
    cudaGetSymbolAddress((void**)&kp,  g_k);
    cudaGetSymbolAddress((void**)&vp,  g_v);
    cudaGetSymbolAddress((void**)&ot,  g_ot);

    cudaFuncSetAttribute(flash_mma, cudaFuncAttributeMaxDynamicSharedMemorySize, FL_SMEM);
    cudaFuncSetAttribute(qkv_gemm, cudaFuncAttributeMaxDynamicSharedMemorySize, GEMM_SMEM);
    cudaFuncSetAttribute(out_gemm, cudaFuncAttributeMaxDynamicSharedMemorySize, GEMM_SMEM);

    // Split x into fp16 hi/lo; convert 4 weights to single fp16
    {
        int n4x = MROWS * DIM_ / 4;
        int n4w = DIM_ * DIM_ / 4;
        split_kernel<<<n4x / 256, 256>>>(x, xhi, xlo, n4x);
        dim3 g4(n4w / 256, 4);
        conv4_kernel<<<g4, 256>>>(Wq, Wk, Wv, Wo, wq, wk, wv, wo, n4w);
    }

    // Fused QKV projections — one launch
    dim3 gqkv(DIM_ / GBN, MROWS / GBM, 3);   // (16, 32, 3) = 1536 CTAs
    qkv_gemm<<<gqkv, 256, GEMM_SMEM>>>(xhi, xlo, wq, wk, wv,
                                       qhi, qlo, kp, vp, cosb, sinb);

    // Tensor-core causal flash attention -> ot transposed (single fp16)
    dim3 gflash(S_ / 64, H_, B_);            // (32, 16, 2)
    flash_mma<<<gflash, 128, FL_SMEM>>>(qhi, qlo, kp, vp, ot);

    // Output projection (fp32 out, 1-pass)
    dim3 ggemm(DIM_ / GBN, MROWS / GBM);     // (16, 32)
    out_gemm<<<ggemm, 256, GEMM_SMEM>>>(ot, wo, (float*)d_out);
}

// round 14
// speedup vs baseline: 2.1876x; 1.1642x over previous
#include <cuda_runtime.h>
#include <cuda_fp16.h>
#include <cstdint>
#include <math.h>

// Problem constants
#define B_    2
#define S_    2048
#define DIM_  2048
#define H_    16
#define DH_   128
#define MROWS (B_ * S_)   // 4096

// ---------------------------------------------------------------------------
// Scratch (allocation-free rule: device globals)
// ---------------------------------------------------------------------------
__device__ __half g_xhi [MROWS * DIM_];
__device__ __half g_xlo [MROWS * DIM_];
__device__ __half g_wq  [DIM_ * DIM_];
__device__ __half g_wk  [DIM_ * DIM_];
__device__ __half g_wv  [DIM_ * DIM_];
__device__ __half g_wo  [DIM_ * DIM_];
__device__ __half g_q   [MROWS * DIM_];
__device__ __half g_k   [MROWS * DIM_];
__device__ __half g_v   [MROWS * DIM_];
__device__ __half g_ot  [MROWS * DIM_];

// ---------------------------------------------------------------------------
// Helpers
// ---------------------------------------------------------------------------
__device__ __forceinline__ uint32_t smem_u32(const void* p) {
    uint32_t a;
    asm("{ .reg .u64 t; cvta.to.shared.u64 t, %1; cvt.u32.u64 %0, t; }" : "=r"(a) : "l"(p));
    return a;
}
__device__ __forceinline__ void cp_async16(uint32_t dst, const void* src) {
    asm volatile("cp.async.cg.shared.global [%0], [%1], 16;" :: "r"(dst), "l"(src));
}
#define CP_COMMIT() asm volatile("cp.async.commit_group;" ::: "memory")
#define CP_WAIT(n)  asm volatile("cp.async.wait_group %0;" :: "n"(n) : "memory")

__device__ __forceinline__ void ldmatrix_x4(uint32_t& r0, uint32_t& r1,
                                            uint32_t& r2, uint32_t& r3, uint32_t addr) {
    asm volatile("ldmatrix.sync.aligned.m8n8.x4.shared.b16 {%0,%1,%2,%3}, [%4];"
                 : "=r"(r0), "=r"(r1), "=r"(r2), "=r"(r3) : "r"(addr));
}
__device__ __forceinline__ void ldmatrix_x4_trans(uint32_t& r0, uint32_t& r1,
                                                  uint32_t& r2, uint32_t& r3, uint32_t addr) {
    asm volatile("ldmatrix.sync.aligned.m8n8.x4.trans.shared.b16 {%0,%1,%2,%3}, [%4];"
                 : "=r"(r0), "=r"(r1), "=r"(r2), "=r"(r3) : "r"(addr));
}
__device__ __forceinline__ void mma_f16(float* c, const uint32_t* a, const uint32_t* b) {
    asm volatile(
        "mma.sync.aligned.m16n8k16.row.col.f32.f16.f16.f32 "
        "{%0,%1,%2,%3}, {%4,%5,%6,%7}, {%8,%9}, {%0,%1,%2,%3};"
        : "+f"(c[0]), "+f"(c[1]), "+f"(c[2]), "+f"(c[3])
        : "r"(a[0]), "r"(a[1]), "r"(a[2]), "r"(a[3]), "r"(b[0]), "r"(b[1]));
}

// Fast exp2 (degree-5 poly on FMA pipe, avoids MUFU bottleneck)
__device__ __forceinline__ float fexp2(float x) {
    x = fmaxf(x, -80.f);
    float f = x + 12582912.f;
    int  n  = __float_as_int(f) - 0x4B400000;
    float r = x - (f - 12582912.f);
    float p =            1.3333558146e-3f;
    p = fmaf(p, r, 9.6181291076e-3f);
    p = fmaf(p, r, 5.5504108665e-2f);
    p = fmaf(p, r, 2.4022650696e-1f);
    p = fmaf(p, r, 6.9314718056e-1f);
    p = fmaf(p, r, 1.0f);
    return __int_as_float(__float_as_int(p) + (n << 23));
}

// fp16 split: x = hi + lo with ~22-bit combined mantissa
__device__ __forceinline__ void split_pack_h(float x, float y, uint32_t& hi, uint32_t& lo) {
    __half2 h = __float22half2_rn(make_float2(x, y));
    float2 hb = __half22float2(h);
    __half2 l = __float22half2_rn(make_float2(x - hb.x, y - hb.y));
    hi = *(uint32_t*)&h;
    lo = *(uint32_t*)&l;
}
__device__ __forceinline__ uint32_t pack_h(float x, float y) {
    __half2 h = __float22half2_rn(make_float2(x, y));
    return *(uint32_t*)&h;
}

// ---------------------------------------------------------------------------
// Split fp32 -> (fp16 hi, fp16 lo). Vectorized by 4.
// ---------------------------------------------------------------------------
__global__ void split_kernel(const float* __restrict__ in,
                             __half* __restrict__ hi,
                             __half* __restrict__ lo, int n4)
{
    int i = blockIdx.x * blockDim.x + threadIdx.x;
    if (i >= n4) return;
    float4 v = ((const float4*)in)[i];
    uint32_t h0, l0, h1, l1;
    split_pack_h(v.x, v.y, h0, l0);
    split_pack_h(v.z, v.w, h1, l1);
    ((uint32_t*)hi)[2 * i]     = h0;
    ((uint32_t*)hi)[2 * i + 1] = h1;
    ((uint32_t*)lo)[2 * i]     = l0;
    ((uint32_t*)lo)[2 * i + 1] = l1;
}

// Convert 4 weights to single fp16 in one launch (blockIdx.y selects)
__global__ void conv4_kernel(const float* __restrict__ w0, const float* __restrict__ w1,
                             const float* __restrict__ w2, const float* __restrict__ w3,
                             __half* __restrict__ h0, __half* __restrict__ h1,
                             __half* __restrict__ h2, __half* __restrict__ h3, int n4)
{
    int i = blockIdx.x * blockDim.x + threadIdx.x;
    if (i >= n4) return;
    const float* in; __half* out;
    switch (blockIdx.y) {
        case 0: in = w0; out = h0; break;
        case 1: in = w1; out = h1; break;
        case 2: in = w2; out = h2; break;
        default: in = w3; out = h3; break;
    }
    float4 v = ((const float4*)in)[i];
    ((uint32_t*)out)[2 * i]     = pack_h(v.x, v.y);
    ((uint32_t*)out)[2 * i + 1] = pack_h(v.z, v.w);
}

// ---------------------------------------------------------------------------
// GEMM core: 2-stage, 2 syncs/iter, BK=64, PASSES in {1,2}:
//   PASSES=2: C = Ahi@B^T + Alo@B^T ; PASSES=1: C = Ahi@B^T
// Stage = A(16KB) + B(16KB); 2 stages = 64KB dynamic smem, 2 CTAs/SM.
// Block 128x128, 256 threads (8 warps = 4M x 2N).
// ---------------------------------------------------------------------------
#define GBM 128
#define GBN 128
#define GBK 64
#define GSTAGE 32768
#define GEMM_SMEM (2 * GSTAGE)
__device__ __forceinline__ uint32_t swg(int r, int c) {
    return (uint32_t)(r * 128 + ((c ^ (r & 7)) << 4));
}

template <int PASSES>
__device__ __forceinline__ void gemm_core(
    const __half* __restrict__ Ahi, const __half* __restrict__ Alo,
    const __half* __restrict__ Bs,
    int bm, int bn, int K, char* sm, float acc[2][8][4])
{
    const int tid  = threadIdx.x;
    const int wid  = tid >> 5;
    const int lane = tid & 31;
    const int mbase = (wid & 3) * 32;
    const int nbase = (wid >> 2) * 64;

    const uint32_t sBase = smem_u32(sm);

    const __half* Asegs[2] = {Ahi, Alo};

    const int KIT = K / GBK;          // 32
    const int NIT = PASSES * KIT;

    auto issue = [&](int it, int buf) {
        const uint32_t st = sBase + (uint32_t)buf * GSTAGE;
        const int seg = it / KIT;
        const int k0  = (it % KIT) * GBK;
        const __half* A = Asegs[seg];
#pragma unroll
        for (int i = 0; i < 4; i++) {
            int id = i * 256 + tid;
            int r = id >> 3, c = id & 7;
            uint32_t off = swg(r, c);
            cp_async16(st + off,         A  + (size_t)(bm + r) * K + k0 + c * 8);
            cp_async16(st + 16384 + off, Bs + (size_t)(bn + r) * K + k0 + c * 8);
        }
        CP_COMMIT();
    };

#pragma unroll
    for (int mt = 0; mt < 2; mt++)
#pragma unroll
        for (int nt = 0; nt < 8; nt++)
#pragma unroll
            for (int e = 0; e < 4; e++) acc[mt][nt][e] = 0.f;

    issue(0, 0);

    for (int it = 0; it < NIT; it++) {
        const int buf = it & 1;
        if (it + 1 < NIT) {
            issue(it + 1, buf ^ 1);
            CP_WAIT(1);
        } else {
            CP_WAIT(0);
        }
        __syncthreads();

        const uint32_t sA = sBase + (uint32_t)buf * GSTAGE;
        const uint32_t sB = sA + 16384;

#pragma unroll
        for (int ks = 0; ks < 4; ks++) {
            uint32_t afr[2][4];
#pragma unroll
            for (int mt = 0; mt < 2; mt++) {
                int row   = mbase + mt * 16 + (lane & 15);
                int chunk = ks * 2 + (lane >> 4);
                ldmatrix_x4(afr[mt][0], afr[mt][1], afr[mt][2], afr[mt][3],
                            sA + swg(row, chunk));
            }
            uint32_t bfr[8][2];
#pragma unroll
            for (int nt2 = 0; nt2 < 4; nt2++) {
                int row   = nbase + nt2 * 16 + ((lane >> 4) << 3) + (lane & 7);
                int chunk = ks * 2 + ((lane >> 3) & 1);
                ldmatrix_x4(bfr[nt2 * 2][0], bfr[nt2 * 2][1],
                            bfr[nt2 * 2 + 1][0], bfr[nt2 * 2 + 1][1],
                            sB + swg(row, chunk));
            }
#pragma unroll
            for (int mt = 0; mt < 2; mt++)
#pragma unroll
                for (int nt = 0; nt < 8; nt++)
                    mma_f16(acc[mt][nt], afr[mt], bfr[nt]);
        }
        __syncthreads();
    }
}

// ---------------------------------------------------------------------------
// Fused QKV GEMM: blockIdx.z selects {Wq(rope, 2-pass), Wk(rope, 1-pass),
//                                     Wv(1-pass)}. All outputs single fp16.
// ---------------------------------------------------------------------------
__global__ __launch_bounds__(256, 2) void qkv_gemm(
    const __half* __restrict__ xhi, const __half* __restrict__ xlo,
    const __half* __restrict__ wq, const __half* __restrict__ wk,
    const __half* __restrict__ wv,
    __half* __restrict__ qq, __half* __restrict__ kk, __half* __restrict__ vv,
    const float* __restrict__ cosb, const float* __restrict__ sinb)
{
    extern __shared__ __align__(1024) char smq[];

    const int bm = blockIdx.y * GBM;
    const int bn = blockIdx.x * GBN;
    const int z  = blockIdx.z;

    float acc[2][8][4];
    if (z == 0)      gemm_core<2>(xhi, xlo, wq, bm, bn, DIM_, smq, acc);
    else if (z == 1) gemm_core<1>(xhi, xhi, wk, bm, bn, DIM_, smq, acc);
    else             gemm_core<1>(xhi, xhi, wv, bm, bn, DIM_, smq, acc);

    __half* out = (z == 0) ? qq : (z == 1) ? kk : vv;

    const int lane = threadIdx.x & 31;
    const int wid  = threadIdx.x >> 5;
    const int mbase = (wid & 3) * 32;
    const int nbase = (wid >> 2) * 64;
    const int erow = lane >> 2;
    const int ecol = (lane & 3) * 2;
#pragma unroll
    for (int mt = 0; mt < 2; mt++) {
#pragma unroll
        for (int nt = 0; nt < 8; nt++) {
            const int grow = bm + mbase + mt * 16 + erow;
            const int gcol = bn + nbase + nt * 8 + ecol;
            float v0 = acc[mt][nt][0], v1 = acc[mt][nt][1];
            float v2 = acc[mt][nt][2], v3 = acc[mt][nt][3];
            if (z < 2) {   // RoPE for q and k
                const int fi = (gcol & 127) >> 1;
                const int s0 = grow & (S_ - 1);
                const int s1 = (grow + 8) & (S_ - 1);
                float c0 = cosb[s0 * 64 + fi], n0 = sinb[s0 * 64 + fi];
                float c1 = cosb[s1 * 64 + fi], n1 = sinb[s1 * 64 + fi];
                float r0 = v0 * c0 - v1 * n0, i0 = v0 * n0 + v1 * c0;
                float r1 = v2 * c1 - v3 * n1, i1 = v2 * n1 + v3 * c1;
                v0 = r0; v1 = i0; v2 = r1; v3 = i1;
            }
            size_t o0 = (size_t)grow * DIM_ + gcol;
            size_t o1 = o0 + (size_t)8 * DIM_;
            *(uint32_t*)(out + o0) = pack_h(v0, v1);
            *(uint32_t*)(out + o1) = pack_h(v2, v3);
        }
    }
}

// Output projection GEMM (fp32 out): A = Ot single fp16, 1-pass
__global__ __launch_bounds__(256, 2) void out_gemm(
    const __half* __restrict__ As, const __half* __restrict__ Bs,
    float* __restrict__ C)
{
    extern __shared__ __align__(1024) char smo[];
    const int bm = blockIdx.y * GBM;
    const int bn = blockIdx.x * GBN;

    float acc[2][8][4];
    gemm_core<1>(As, As, Bs, bm, bn, DIM_, smo, acc);

    const int lane = threadIdx.x & 31;
    const int wid  = threadIdx.x >> 5;
    const int mbase = (wid & 3) * 32;
    const int nbase = (wid >> 2) * 64;
    const int erow = lane >> 2;
    const int ecol = (lane & 3) * 2;
#pragma unroll
    for (int mt = 0; mt < 2; mt++) {
#pragma unroll
        for (int nt = 0; nt < 8; nt++) {
            const int grow = bm + mbase + mt * 16 + erow;
            const int gcol = bn + nbase + nt * 8 + ecol;
            float* cp0 = C + (size_t)grow * DIM_ + gcol;
            *(float2*)cp0              = make_float2(acc[mt][nt][0], acc[mt][nt][1]);
            *(float2*)(cp0 + 8 * DIM_) = make_float2(acc[mt][nt][2], acc[mt][nt][3]);
        }
    }
}

// ---------------------------------------------------------------------------
// Flash attention: FA2 on tensor cores, all-fp16 single-pass (QK and PV).
// CTA: 64 q-rows, 4 warps, kv tiles of 32 rows, double-buffered.
// smem: Q 16K + 2 stages x (K 8K + V 8K) = 48KB, 2 CTAs/SM.
// ---------------------------------------------------------------------------
#define FL_SMEM 49152

__device__ __forceinline__ uint32_t fl_off(int r, int c) {
    return (uint32_t)(r * 256 + ((c ^ (r & 7)) << 4));
}

__global__ __launch_bounds__(128, 2) void flash_mma(
    const __half* __restrict__ qq, const __half* __restrict__ kk,
    const __half* __restrict__ vv, __half* __restrict__ ot)
{
    extern __shared__ __align__(1024) char sm8[];
    const uint32_t sQ = smem_u32(sm8);

    const int qb = (int)gridDim.x - 1 - blockIdx.x;   // largest first
    const int h = blockIdx.y, b = blockIdx.z;
    const int qbase = qb * 64;
    const int tid = threadIdx.x, wid = tid >> 5, lane = tid & 31;
    const int mbase = wid * 16;
    const int colbase = h * DH_;
    const size_t rowg0 = ((size_t)b * S_ + qbase) * DIM_ + colbase;

#pragma unroll
    for (int i = 0; i < 8; i++) {
        int idx = i * 128 + tid;
        int r = idx >> 4, c = idx & 15;
        size_t g = rowg0 + (size_t)r * DIM_ + c * 8;
        cp_async16(sQ + fl_off(r, c), qq + g);
    }
    CP_COMMIT();

    const int NT = 2 * qb + 2;

    auto issueKV = [&](int kb, int st) {
        const uint32_t base = sQ + 16384 + st * 16384;
        const size_t krow0 = ((size_t)b * S_ + kb * 32) * DIM_ + colbase;
#pragma unroll
        for (int i = 0; i < 4; i++) {
            int idx = i * 128 + tid;
            int r = idx >> 4, c = idx & 15;
            uint32_t off = fl_off(r, c);
            size_t g = krow0 + (size_t)r * DIM_ + c * 8;
            cp_async16(base + off,        kk + g);
            cp_async16(base + 8192 + off, vv + g);
        }
        CP_COMMIT();
    };

    issueKV(0, 0);

    float m0 = -1e30f, m1 = -1e30f, l0 = 0.f, l1 = 0.f;
    float o[16][4];
#pragma unroll
    for (int nt = 0; nt < 16; nt++)
#pragma unroll
        for (int e = 0; e < 4; e++) o[nt][e] = 0.f;

    const int rA = lane >> 2;
    const int cq = (lane & 3) * 2;
    const float KARG = 0.1275166782f;   // (1/sqrt(128)) * log2(e)

    const int a_r  = (lane & 7) + ((lane >> 3) & 1) * 8;
    const int a_cb = lane >> 4;
    const int bk_r = (lane & 7);
    const int bk_np = lane >> 4;
    const int bk_cb = (lane >> 3) & 1;

    for (int kb = 0; kb < NT; kb++) {
        const int st = kb & 1;
        const uint32_t sK = sQ + 16384 + st * 16384;
        const uint32_t sV = sK + 8192;

        __syncthreads();
        if (kb + 1 < NT) {
            issueKV(kb + 1, st ^ 1);
            CP_WAIT(1);
        } else {
            CP_WAIT(0);
        }
        __syncthreads();

        const bool active = (kb * 32) <= (qbase + mbase + 15);
        if (active) {
            // ---- S = Q @ K^T (single-pass fp16) ----
            float sacc[4][4];
#pragma unroll
            for (int nt = 0; nt < 4; nt++)
#pragma unroll
                for (int e = 0; e < 4; e++) sacc[nt][e] = 0.f;

#pragma unroll
            for (int kkk = 0; kkk < 8; kkk++) {
                uint32_t aq[4], bk[4][2];
                int arow = mbase + a_r;
                int achk = 2 * kkk + a_cb;
                ldmatrix_x4(aq[0], aq[1], aq[2], aq[3], sQ + fl_off(arow, achk));
#pragma unroll
                for (int np = 0; np < 2; np++) {
                    int brow = (2 * np + bk_np) * 8 + bk_r;
                    int bchk = 2 * kkk + bk_cb;
                    ldmatrix_x4(bk[2 * np][0], bk[2 * np][1],
                                bk[2 * np + 1][0], bk[2 * np + 1][1],
                                sK + fl_off(brow, bchk));
                }
#pragma unroll
                for (int nt = 0; nt < 4; nt++) mma_f16(sacc[nt], aq, bk[nt]);
            }

            if (kb * 32 + 31 > qbase + mbase) {
                int rowA = qbase + mbase + rA, rowB = rowA + 8;
#pragma unroll
                for (int nt = 0; nt < 4; nt++) {
                    int c0 = kb * 32 + nt * 8 + cq;
                    if (c0     > rowA) sacc[nt][0] = -1e30f;
                    if (c0 + 1 > rowA) sacc[nt][1] = -1e30f;
                    if (c0     > rowB) sacc[nt][2] = -1e30f;
                    if (c0 + 1 > rowB) sacc[nt][3] = -1e30f;
                }
            }

            float tmA = -1e30f, tmB = -1e30f;
#pragma unroll
            for (int nt = 0; nt < 4; nt++) {
                tmA = fmaxf(tmA, fmaxf(sacc[nt][0], sacc[nt][1]));
                tmB = fmaxf(tmB, fmaxf(sacc[nt][2], sacc[nt][3]));
            }
            tmA = fmaxf(tmA, __shfl_xor_sync(0xffffffffu, tmA, 1));
            tmA = fmaxf(tmA, __shfl_xor_sync(0xffffffffu, tmA, 2));
            tmB = fmaxf(tmB, __shfl_xor_sync(0xffffffffu, tmB, 1));
            tmB = fmaxf(tmB, __shfl_xor_sync(0xffffffffu, tmB, 2));

            float alpha0 = 1.f, alpha1 = 1.f;
            bool upd0 = (tmA > m0), upd1 = (tmB > m1);
            if (upd0) { alpha0 = fexp2((m0 - tmA) * KARG); m0 = tmA; }
            if (upd1) { alpha1 = fexp2((m1 - tmB) * KARG); m1 = tmB; }

            float rs0 = 0.f, rs1 = 0.f;
#pragma unroll
            for (int nt = 0; nt < 4; nt++) {
                float p0 = fexp2((sacc[nt][0] - m0) * KARG);
                float p1 = fexp2((sacc[nt][1] - m0) * KARG);
                float p2 = fexp2((sacc[nt][2] - m1) * KARG);
                float p3 = fexp2((sacc[nt][3] - m1) * KARG);
                sacc[nt][0] = p0; sacc[nt][1] = p1; sacc[nt][2] = p2; sacc[nt][3] = p3;
                rs0 += p0 + p1; rs1 += p2 + p3;
            }
            rs0 += __shfl_xor_sync(0xffffffffu, rs0, 1);
            rs0 += __shfl_xor_sync(0xffffffffu, rs0, 2);
            rs1 += __shfl_xor_sync(0xffffffffu, rs1, 1);
            rs1 += __shfl_xor_sync(0xffffffffu, rs1, 2);
            l0 = alpha0 * l0 + rs0;
            l1 = alpha1 * l1 + rs1;

            if (upd0 || upd1) {
#pragma unroll
                for (int nt = 0; nt < 16; nt++) {
                    o[nt][0] *= alpha0; o[nt][1] *= alpha0;
                    o[nt][2] *= alpha1; o[nt][3] *= alpha1;
                }
            }

            // ---- pack P (single fp16) ----
            uint32_t phi[2][4];
#pragma unroll
            for (int kk2 = 0; kk2 < 2; kk2++) {
                phi[kk2][0] = pack_h(sacc[2 * kk2][0],     sacc[2 * kk2][1]);
                phi[kk2][1] = pack_h(sacc[2 * kk2][2],     sacc[2 * kk2][3]);
                phi[kk2][2] = pack_h(sacc[2 * kk2 + 1][0], sacc[2 * kk2 + 1][1]);
                phi[kk2][3] = pack_h(sacc[2 * kk2 + 1][2], sacc[2 * kk2 + 1][3]);
            }

            // ---- O += P @ V (single-pass) ----
#pragma unroll
            for (int kk2 = 0; kk2 < 2; kk2++) {
#pragma unroll
                for (int np = 0; np < 8; np++) {
                    uint32_t bv[4];
                    int vrow = kk2 * 16 + a_r;
                    int vchk = 2 * np + a_cb;
                    ldmatrix_x4_trans(bv[0], bv[1], bv[2], bv[3], sV + fl_off(vrow, vchk));
                    mma_f16(o[2 * np],     phi[kk2], bv + 0);
                    mma_f16(o[2 * np + 1], phi[kk2], bv + 2);
                }
            }
        }
    }

    // ---- epilogue: Ot[b, colbase+col, s] = o / l, single fp16 ----
    const float inv0 = 1.f / l0, inv1 = 1.f / l1;
    const int s0 = qbase + mbase + rA;
    const int s1 = s0 + 8;
#pragma unroll
    for (int nt = 0; nt < 16; nt++) {
        int col = colbase + nt * 8 + cq;
        size_t i00 = ((size_t)b * DIM_ + col) * S_;
        size_t i01 = i00 + S_;
        ot[i00 + s0] = __float2half_rn(o[nt][0] * inv0);
        ot[i01 + s0] = __float2half_rn(o[nt][1] * inv0);
        ot[i00 + s1] = __float2half_rn(o[nt][2] * inv1);
        ot[i01 + s1] = __float2half_rn(o[nt][3] * inv1);
    }
}

// ---------------------------------------------------------------------------
// Launch
// ---------------------------------------------------------------------------
extern "C" void kernel_launch(void* const* d_in, const int* in_sizes, int n_in,
                              void* d_out, int out_size)
{
    const float* x    = (const float*)d_in[0];
    const float* Wq   = (const float*)d_in[1];
    const float* Wk   = (const float*)d_in[2];
    const float* Wv   = (const float*)d_in[3];
    const float* Wo   = (const float*)d_in[4];
    const float* cosb = (const float*)d_in[5];
    const float* sinb = (const float*)d_in[6];
    // d_in[7] = mask: causal handled analytically

    __half *xhi, *xlo, *wq, *wk, *wv, *wo, *qp, *kp, *vp, *ot;
    cudaGetSymbolAddress((void**)&xhi, g_xhi);
    cudaGetSymbolAddress((void**)&xlo, g_xlo);
    cudaGetSymbolAddress((void**)&wq,  g_wq);
    cudaGetSymbolAddress((void**)&wk,  g_wk);
    cudaGetSymbolAddress((void**)&wv,  g_wv);
    cudaGetSymbolAddress((void**)&wo,  g_wo);
    cudaGetSymbolAddress((void**)&qp,  g_q);
    cudaGetSymbolAddress((void**)&kp,  g_k);
    cudaGetSymbolAddress((void**)&vp,  g_v);
    cudaGetSymbolAddress((void**)&ot,  g_ot);

    cudaFuncSetAttribute(flash_mma, cudaFuncAttributeMaxDynamicSharedMemorySize, FL_SMEM);
    cudaFuncSetAttribute(qkv_gemm, cudaFuncAttributeMaxDynamicSharedMemorySize, GEMM_SMEM);
    cudaFuncSetAttribute(out_gemm, cudaFuncAttributeMaxDynamicSharedMemorySize, GEMM_SMEM);

    // Split x into fp16 hi/lo; convert 4 weights to single fp16
    {
        int n4x = MROWS * DIM_ / 4;
        int n4w = DIM_ * DIM_ / 4;
        split_kernel<<<n4x / 256, 256>>>(x, xhi, xlo, n4x);
        dim3 g4(n4w / 256, 4);
        conv4_kernel<<<g4, 256>>>(Wq, Wk, Wv, Wo, wq, wk, wv, wo, n4w);
    }

    // Fused QKV projections — one launch
    dim3 gqkv(DIM_ / GBN, MROWS / GBM, 3);   // (16, 32, 3) = 1536 CTAs
    qkv_gemm<<<gqkv, 256, GEMM_SMEM>>>(xhi, xlo, wq, wk, wv,
                                       qp, kp, vp, cosb, sinb);

    // Tensor-core causal flash attention -> ot transposed (single fp16)
    dim3 gflash(S_ / 64, H_, B_);            // (32, 16, 2)
    flash_mma<<<gflash, 128, FL_SMEM>>>(qp, kp, vp, ot);

    // Output projection (fp32 out, 1-pass)
    dim3 ggemm(DIM_ / GBN, MROWS / GBM);     // (16, 32)
    out_gemm<<<ggemm, 256, GEMM_SMEM>>>(ot, wo, (float*)d_out);
}

// round 15
// speedup vs baseline: 2.5536x; 1.1673x over previous
#include <cuda_runtime.h>
#include <cuda_fp16.h>
#include <cstdint>
#include <math.h>

// Problem constants
#define B_    2
#define S_    2048
#define DIM_  2048
#define H_    16
#define DH_   128
#define MROWS (B_ * S_)   // 4096

// ---------------------------------------------------------------------------
// Scratch (allocation-free rule: device globals)
// ---------------------------------------------------------------------------
__device__ __half g_x  [MROWS * DIM_];
__device__ __half g_wq [DIM_ * DIM_];
__device__ __half g_wk [DIM_ * DIM_];
__device__ __half g_wv [DIM_ * DIM_];
__device__ __half g_wo [DIM_ * DIM_];
__device__ __half g_q  [MROWS * DIM_];
__device__ __half g_k  [MROWS * DIM_];
__device__ __half g_v  [MROWS * DIM_];
__device__ __half g_ot [MROWS * DIM_];

// ---------------------------------------------------------------------------
// Helpers
// ---------------------------------------------------------------------------
__device__ __forceinline__ uint32_t smem_u32(const void* p) {
    uint32_t a;
    asm("{ .reg .u64 t; cvta.to.shared.u64 t, %1; cvt.u32.u64 %0, t; }" : "=r"(a) : "l"(p));
    return a;
}
__device__ __forceinline__ void cp_async16(uint32_t dst, const void* src) {
    asm volatile("cp.async.cg.shared.global [%0], [%1], 16;" :: "r"(dst), "l"(src));
}
#define CP_COMMIT() asm volatile("cp.async.commit_group;" ::: "memory")
#define CP_WAIT(n)  asm volatile("cp.async.wait_group %0;" :: "n"(n) : "memory")

__device__ __forceinline__ void ldmatrix_x4(uint32_t& r0, uint32_t& r1,
                                            uint32_t& r2, uint32_t& r3, uint32_t addr) {
    asm volatile("ldmatrix.sync.aligned.m8n8.x4.shared.b16 {%0,%1,%2,%3}, [%4];"
                 : "=r"(r0), "=r"(r1), "=r"(r2), "=r"(r3) : "r"(addr));
}
__device__ __forceinline__ void ldmatrix_x4_trans(uint32_t& r0, uint32_t& r1,
                                                  uint32_t& r2, uint32_t& r3, uint32_t addr) {
    asm volatile("ldmatrix.sync.aligned.m8n8.x4.trans.shared.b16 {%0,%1,%2,%3}, [%4];"
                 : "=r"(r0), "=r"(r1), "=r"(r2), "=r"(r3) : "r"(addr));
}
__device__ __forceinline__ void mma_f16(float* c, const uint32_t* a, const uint32_t* b) {
    asm volatile(
        "mma.sync.aligned.m16n8k16.row.col.f32.f16.f16.f32 "
        "{%0,%1,%2,%3}, {%4,%5,%6,%7}, {%8,%9}, {%0,%1,%2,%3};"
        : "+f"(c[0]), "+f"(c[1]), "+f"(c[2]), "+f"(c[3])
        : "r"(a[0]), "r"(a[1]), "r"(a[2]), "r"(a[3]), "r"(b[0]), "r"(b[1]));
}

// Fast exp2 (degree-5 poly on FMA pipe, avoids MUFU bottleneck)
__device__ __forceinline__ float fexp2(float x) {
    x = fmaxf(x, -80.f);
    float f = x + 12582912.f;
    int  n  = __float_as_int(f) - 0x4B400000;
    float r = x - (f - 12582912.f);
    float p =            1.3333558146e-3f;
    p = fmaf(p, r, 9.6181291076e-3f);
    p = fmaf(p, r, 5.5504108665e-2f);
    p = fmaf(p, r, 2.4022650696e-1f);
    p = fmaf(p, r, 6.9314718056e-1f);
    p = fmaf(p, r, 1.0f);
    return __int_as_float(__float_as_int(p) + (n << 23));
}

__device__ __forceinline__ uint32_t pack_h(float x, float y) {
    __half2 h = __float22half2_rn(make_float2(x, y));
    return *(uint32_t*)&h;
}

// ---------------------------------------------------------------------------
// Convert x + 4 weights to fp16 in one grid (blockIdx.y: 0..3 weights, 4..5 x)
// Weights n4 = DIM*DIM/4; x handled as two weight-sized slabs.
// ---------------------------------------------------------------------------
__global__ void conv_all_kernel(const float* __restrict__ x,
                                const float* __restrict__ w0, const float* __restrict__ w1,
                                const float* __restrict__ w2, const float* __restrict__ w3,
                                __half* __restrict__ xh,
                                __half* __restrict__ h0, __half* __restrict__ h1,
                                __half* __restrict__ h2, __half* __restrict__ h3, int n4)
{
    int i = blockIdx.x * blockDim.x + threadIdx.x;
    if (i >= n4) return;
    const float* in; __half* out;
    switch (blockIdx.y) {
        case 0: in = w0; out = h0; break;
        case 1: in = w1; out = h1; break;
        case 2: in = w2; out = h2; break;
        case 3: in = w3; out = h3; break;
        case 4: in = x;            out = xh;            break;
        default: in = x + 4 * (size_t)n4; out = xh + 4 * (size_t)n4; break;
    }
    float4 v = ((const float4*)in)[i];
    ((uint32_t*)out)[2 * i]     = pack_h(v.x, v.y);
    ((uint32_t*)out)[2 * i + 1] = pack_h(v.z, v.w);
}

// ---------------------------------------------------------------------------
// GEMM core: 2-stage, 2 syncs/iter, BK=64, single pass fp16:
//   C = A@B^T  (fp32 accum)
// Stage = A(16KB) + B(16KB); 2 stages = 64KB dynamic smem, 2 CTAs/SM.
// Block 128x128, 256 threads (8 warps = 4M x 2N).
// ---------------------------------------------------------------------------
#define GBM 128
#define GBN 128
#define GBK 64
#define GSTAGE 32768
#define GEMM_SMEM (2 * GSTAGE)
__device__ __forceinline__ uint32_t swg(int r, int c) {
    return (uint32_t)(r * 128 + ((c ^ (r & 7)) << 4));
}

__device__ __forceinline__ void gemm_core(
    const __half* __restrict__ As, const __half* __restrict__ Bs,
    int bm, int bn, int K, char* sm, float acc[2][8][4])
{
    const int tid  = threadIdx.x;
    const int wid  = tid >> 5;
    const int lane = tid & 31;
    const int mbase = (wid & 3) * 32;
    const int nbase = (wid >> 2) * 64;

    const uint32_t sBase = smem_u32(sm);
    const int NIT = K / GBK;          // 32

    auto issue = [&](int it, int buf) {
        const uint32_t st = sBase + (uint32_t)buf * GSTAGE;
        const int k0 = it * GBK;
#pragma unroll
        for (int i = 0; i < 4; i++) {
            int id = i * 256 + tid;
            int r = id >> 3, c = id & 7;
            uint32_t off = swg(r, c);
            cp_async16(st + off,         As + (size_t)(bm + r) * K + k0 + c * 8);
            cp_async16(st + 16384 + off, Bs + (size_t)(bn + r) * K + k0 + c * 8);
        }
        CP_COMMIT();
    };

#pragma unroll
    for (int mt = 0; mt < 2; mt++)
#pragma unroll
        for (int nt = 0; nt < 8; nt++)
#pragma unroll
            for (int e = 0; e < 4; e++) acc[mt][nt][e] = 0.f;

    issue(0, 0);

    for (int it = 0; it < NIT; it++) {
        const int buf = it & 1;
        if (it + 1 < NIT) {
            issue(it + 1, buf ^ 1);
            CP_WAIT(1);
        } else {
            CP_WAIT(0);
        }
        __syncthreads();

        const uint32_t sA = sBase + (uint32_t)buf * GSTAGE;
        const uint32_t sB = sA + 16384;

#pragma unroll
        for (int ks = 0; ks < 4; ks++) {
            uint32_t afr[2][4];
#pragma unroll
            for (int mt = 0; mt < 2; mt++) {
                int row   = mbase + mt * 16 + (lane & 15);
                int chunk = ks * 2 + (lane >> 4);
                ldmatrix_x4(afr[mt][0], afr[mt][1], afr[mt][2], afr[mt][3],
                            sA + swg(row, chunk));
            }
            uint32_t bfr[8][2];
#pragma unroll
            for (int nt2 = 0; nt2 < 4; nt2++) {
                int row   = nbase + nt2 * 16 + ((lane >> 4) << 3) + (lane & 7);
                int chunk = ks * 2 + ((lane >> 3) & 1);
                ldmatrix_x4(bfr[nt2 * 2][0], bfr[nt2 * 2][1],
                            bfr[nt2 * 2 + 1][0], bfr[nt2 * 2 + 1][1],
                            sB + swg(row, chunk));
            }
#pragma unroll
            for (int mt = 0; mt < 2; mt++)
#pragma unroll
                for (int nt = 0; nt < 8; nt++)
                    mma_f16(acc[mt][nt], afr[mt], bfr[nt]);
        }
        __syncthreads();
    }
}

// ---------------------------------------------------------------------------
// Fused QKV GEMM: blockIdx.z selects {Wq(rope), Wk(rope), Wv}.
// ---------------------------------------------------------------------------
__global__ __launch_bounds__(256, 2) void qkv_gemm(
    const __half* __restrict__ xh,
    const __half* __restrict__ wq, const __half* __restrict__ wk,
    const __half* __restrict__ wv,
    __half* __restrict__ qq, __half* __restrict__ kk, __half* __restrict__ vv,
    const float* __restrict__ cosb, const float* __restrict__ sinb)
{
    extern __shared__ __align__(1024) char smq[];

    const int bm = blockIdx.y * GBM;
    const int bn = blockIdx.x * GBN;
    const int z  = blockIdx.z;

    const __half* Bs = (z == 0) ? wq : (z == 1) ? wk : wv;
    __half* out = (z == 0) ? qq : (z == 1) ? kk : vv;

    float acc[2][8][4];
    gemm_core(xh, Bs, bm, bn, DIM_, smq, acc);

    const int lane = threadIdx.x & 31;
    const int wid  = threadIdx.x >> 5;
    const int mbase = (wid & 3) * 32;
    const int nbase = (wid >> 2) * 64;
    const int erow = lane >> 2;
    const int ecol = (lane & 3) * 2;
#pragma unroll
    for (int mt = 0; mt < 2; mt++) {
#pragma unroll
        for (int nt = 0; nt < 8; nt++) {
            const int grow = bm + mbase + mt * 16 + erow;
            const int gcol = bn + nbase + nt * 8 + ecol;
            float v0 = acc[mt][nt][0], v1 = acc[mt][nt][1];
            float v2 = acc[mt][nt][2], v3 = acc[mt][nt][3];
            if (z < 2) {   // RoPE for q and k
                const int fi = (gcol & 127) >> 1;
                const int s0 = grow & (S_ - 1);
                const int s1 = (grow + 8) & (S_ - 1);
                float c0 = cosb[s0 * 64 + fi], n0 = sinb[s0 * 64 + fi];
                float c1 = cosb[s1 * 64 + fi], n1 = sinb[s1 * 64 + fi];
                float r0 = v0 * c0 - v1 * n0, i0 = v0 * n0 + v1 * c0;
                float r1 = v2 * c1 - v3 * n1, i1 = v2 * n1 + v3 * c1;
                v0 = r0; v1 = i0; v2 = r1; v3 = i1;
            }
            size_t o0 = (size_t)grow * DIM_ + gcol;
            size_t o1 = o0 + (size_t)8 * DIM_;
            *(uint32_t*)(out + o0) = pack_h(v0, v1);
            *(uint32_t*)(out + o1) = pack_h(v2, v3);
        }
    }
}

// Output projection GEMM (fp32 out)
__global__ __launch_bounds__(256, 2) void out_gemm(
    const __half* __restrict__ As, const __half* __restrict__ Bs,
    float* __restrict__ C)
{
    extern __shared__ __align__(1024) char smo[];
    const int bm = blockIdx.y * GBM;
    const int bn = blockIdx.x * GBN;

    float acc[2][8][4];
    gemm_core(As, Bs, bm, bn, DIM_, smo, acc);

    const int lane = threadIdx.x & 31;
    const int wid  = threadIdx.x >> 5;
    const int mbase = (wid & 3) * 32;
    const int nbase = (wid >> 2) * 64;
    const int erow = lane >> 2;
    const int ecol = (lane & 3) * 2;
#pragma unroll
    for (int mt = 0; mt < 2; mt++) {
#pragma unroll
        for (int nt = 0; nt < 8; nt++) {
            const int grow = bm + mbase + mt * 16 + erow;
            const int gcol = bn + nbase + nt * 8 + ecol;
            float* cp0 = C + (size_t)grow * DIM_ + gcol;
            *(float2*)cp0              = make_float2(acc[mt][nt][0], acc[mt][nt][1]);
            *(float2*)(cp0 + 8 * DIM_) = make_float2(acc[mt][nt][2], acc[mt][nt][3]);
        }
    }
}

// ---------------------------------------------------------------------------
// Flash attention: FA2 on tensor cores, fp16 single-pass, kv tiles of 64.
// CTA: 64 q-rows, 4 warps, double-buffered KV.
// smem: Q 16K + 2 stages x (K 16K + V 16K) = 80KB, 2 CTAs/SM.
// ---------------------------------------------------------------------------
#define FL_SMEM 81920

__device__ __forceinline__ uint32_t fl_off(int r, int c) {
    return (uint32_t)(r * 256 + ((c ^ (r & 7)) << 4));
}

__global__ __launch_bounds__(128, 2) void flash_mma(
    const __half* __restrict__ qq, const __half* __restrict__ kk,
    const __half* __restrict__ vv, __half* __restrict__ ot)
{
    extern __shared__ __align__(1024) char sm8[];
    const uint32_t sQ = smem_u32(sm8);

    const int qb = (int)gridDim.x - 1 - blockIdx.x;   // largest first
    const int h = blockIdx.y, b = blockIdx.z;
    const int qbase = qb * 64;
    const int tid = threadIdx.x, wid = tid >> 5, lane = tid & 31;
    const int mbase = wid * 16;
    const int colbase = h * DH_;
    const size_t rowg0 = ((size_t)b * S_ + qbase) * DIM_ + colbase;

#pragma unroll
    for (int i = 0; i < 8; i++) {
        int idx = i * 128 + tid;
        int r = idx >> 4, c = idx & 15;
        size_t g = rowg0 + (size_t)r * DIM_ + c * 8;
        cp_async16(sQ + fl_off(r, c), qq + g);
    }
    CP_COMMIT();

    const int NT = qb + 1;   // kv tiles of 64

    auto issueKV = [&](int kb, int st) {
        const uint32_t base = sQ + 16384 + st * 32768;
        const size_t krow0 = ((size_t)b * S_ + kb * 64) * DIM_ + colbase;
#pragma unroll
        for (int i = 0; i < 8; i++) {
            int idx = i * 128 + tid;
            int r = idx >> 4, c = idx & 15;
            uint32_t off = fl_off(r, c);
            size_t g = krow0 + (size_t)r * DIM_ + c * 8;
            cp_async16(base + off,         kk + g);
            cp_async16(base + 16384 + off, vv + g);
        }
        CP_COMMIT();
    };

    issueKV(0, 0);

    float m0 = -1e30f, m1 = -1e30f, l0 = 0.f, l1 = 0.f;
    float o[16][4];
#pragma unroll
    for (int nt = 0; nt < 16; nt++)
#pragma unroll
        for (int e = 0; e < 4; e++) o[nt][e] = 0.f;

    const int rA = lane >> 2;
    const int cq = (lane & 3) * 2;
    const float KARG = 0.1275166782f;   // (1/sqrt(128)) * log2(e)

    const int a_r  = (lane & 7) + ((lane >> 3) & 1) * 8;
    const int a_cb = lane >> 4;
    const int bk_r = (lane & 7);
    const int bk_np = lane >> 4;
    const int bk_cb = (lane >> 3) & 1;

    for (int kb = 0; kb < NT; kb++) {
        const int st = kb & 1;
        const uint32_t sK = sQ + 16384 + st * 32768;
        const uint32_t sV = sK + 16384;

        __syncthreads();
        if (kb + 1 < NT) {
            issueKV(kb + 1, st ^ 1);
            CP_WAIT(1);
        } else {
            CP_WAIT(0);
        }
        __syncthreads();

        // ---- S = Q @ K^T (single-pass fp16), 16x64 per warp ----
        float sacc[8][4];
#pragma unroll
        for (int nt = 0; nt < 8; nt++)
#pragma unroll
            for (int e = 0; e < 4; e++) sacc[nt][e] = 0.f;

#pragma unroll
        for (int kkk = 0; kkk < 8; kkk++) {
            uint32_t aq[4], bk[8][2];
            int arow = mbase + a_r;
            int achk = 2 * kkk + a_cb;
            ldmatrix_x4(aq[0], aq[1], aq[2], aq[3], sQ + fl_off(arow, achk));
#pragma unroll
            for (int np = 0; np < 4; np++) {
                int brow = (2 * np + bk_np) * 8 + bk_r;
                int bchk = 2 * kkk + bk_cb;
                ldmatrix_x4(bk[2 * np][0], bk[2 * np][1],
                            bk[2 * np + 1][0], bk[2 * np + 1][1],
                            sK + fl_off(brow, bchk));
            }
#pragma unroll
            for (int nt = 0; nt < 8; nt++) mma_f16(sacc[nt], aq, bk[nt]);
        }

        // ---- causal mask (tiles overlapping diagonal) ----
        if (kb * 64 + 63 > qbase + mbase) {
            int rowA = qbase + mbase + rA, rowB = rowA + 8;
#pragma unroll
            for (int nt = 0; nt < 8; nt++) {
                int c0 = kb * 64 + nt * 8 + cq;
                if (c0     > rowA) sacc[nt][0] = -1e30f;
                if (c0 + 1 > rowA) sacc[nt][1] = -1e30f;
                if (c0     > rowB) sacc[nt][2] = -1e30f;
                if (c0 + 1 > rowB) sacc[nt][3] = -1e30f;
            }
        }

        // ---- online softmax ----
        float tmA = -1e30f, tmB = -1e30f;
#pragma unroll
        for (int nt = 0; nt < 8; nt++) {
            tmA = fmaxf(tmA, fmaxf(sacc[nt][0], sacc[nt][1]));
            tmB = fmaxf(tmB, fmaxf(sacc[nt][2], sacc[nt][3]));
        }
        tmA = fmaxf(tmA, __shfl_xor_sync(0xffffffffu, tmA, 1));
        tmA = fmaxf(tmA, __shfl_xor_sync(0xffffffffu, tmA, 2));
        tmB = fmaxf(tmB, __shfl_xor_sync(0xffffffffu, tmB, 1));
        tmB = fmaxf(tmB, __shfl_xor_sync(0xffffffffu, tmB, 2));

        float alpha0 = 1.f, alpha1 = 1.f;
        bool upd0 = (tmA > m0), upd1 = (tmB > m1);
        if (upd0) { alpha0 = fexp2((m0 - tmA) * KARG); m0 = tmA; }
        if (upd1) { alpha1 = fexp2((m1 - tmB) * KARG); m1 = tmB; }

        float rs0 = 0.f, rs1 = 0.f;
#pragma unroll
        for (int nt = 0; nt < 8; nt++) {
            float p0 = fexp2((sacc[nt][0] - m0) * KARG);
            float p1 = fexp2((sacc[nt][1] - m0) * KARG);
            float p2 = fexp2((sacc[nt][2] - m1) * KARG);
            float p3 = fexp2((sacc[nt][3] - m1) * KARG);
            sacc[nt][0] = p0; sacc[nt][1] = p1; sacc[nt][2] = p2; sacc[nt][3] = p3;
            rs0 += p0 + p1; rs1 += p2 + p3;
        }
        rs0 += __shfl_xor_sync(0xffffffffu, rs0, 1);
        rs0 += __shfl_xor_sync(0xffffffffu, rs0, 2);
        rs1 += __shfl_xor_sync(0xffffffffu, rs1, 1);
        rs1 += __shfl_xor_sync(0xffffffffu, rs1, 2);
        l0 = alpha0 * l0 + rs0;
        l1 = alpha1 * l1 + rs1;

        if (upd0 || upd1) {
#pragma unroll
            for (int nt = 0; nt < 16; nt++) {
                o[nt][0] *= alpha0; o[nt][1] *= alpha0;
                o[nt][2] *= alpha1; o[nt][3] *= alpha1;
            }
        }

        // ---- pack P (single fp16), 4 k-groups of 16 ----
        uint32_t phi[4][4];
#pragma unroll
        for (int kk2 = 0; kk2 < 4; kk2++) {
            phi[kk2][0] = pack_h(sacc[2 * kk2][0],     sacc[2 * kk2][1]);
            phi[kk2][1] = pack_h(sacc[2 * kk2][2],     sacc[2 * kk2][3]);
            phi[kk2][2] = pack_h(sacc[2 * kk2 + 1][0], sacc[2 * kk2 + 1][1]);
            phi[kk2][3] = pack_h(sacc[2 * kk2 + 1][2], sacc[2 * kk2 + 1][3]);
        }

        // ---- O += P @ V (single-pass) ----
#pragma unroll
        for (int kk2 = 0; kk2 < 4; kk2++) {
#pragma unroll
            for (int np = 0; np < 8; np++) {
                uint32_t bv[4];
                int vrow = kk2 * 16 + a_r;
                int vchk = 2 * np + a_cb;
                ldmatrix_x4_trans(bv[0], bv[1], bv[2], bv[3], sV + fl_off(vrow, vchk));
                mma_f16(o[2 * np],     phi[kk2], bv + 0);
                mma_f16(o[2 * np + 1], phi[kk2], bv + 2);
            }
        }
    }

    // ---- epilogue: Ot[b, colbase+col, s] = o / l, single fp16 ----
    const float inv0 = 1.f / l0, inv1 = 1.f / l1;
    const int s0 = qbase + mbase + rA;
    const int s1 = s0 + 8;
#pragma unroll
    for (int nt = 0; nt < 16; nt++) {
        int col = colbase + nt * 8 + cq;
        size_t i00 = ((size_t)b * DIM_ + col) * S_;
        size_t i01 = i00 + S_;
        ot[i00 + s0] = __float2half_rn(o[nt][0] * inv0);
        ot[i01 + s0] = __float2half_rn(o[nt][1] * inv0);
        ot[i00 + s1] = __float2half_rn(o[nt][2] * inv1);
        ot[i01 + s1] = __float2half_rn(o[nt][3] * inv1);
    }
}

// ---------------------------------------------------------------------------
// Launch
// ---------------------------------------------------------------------------
extern "C" void kernel_launch(void* const* d_in, const int* in_sizes, int n_in,
                              void* d_out, int out_size)
{
    const float* x    = (const float*)d_in[0];
    const float* Wq   = (const float*)d_in[1];
    const float* Wk   = (const float*)d_in[2];
    const float* Wv   = (const float*)d_in[3];
    const float* Wo   = (const float*)d_in[4];
    const float* cosb = (const float*)d_in[5];
    const float* sinb = (const float*)d_in[6];
    // d_in[7] = mask: causal handled analytically

    __half *xh, *wq, *wk, *wv, *wo, *qp, *kp, *vp, *ot;
    cudaGetSymbolAddress((void**)&xh, g_x);
    cudaGetSymbolAddress((void**)&wq, g_wq);
    cudaGetSymbolAddress((void**)&wk, g_wk);
    cudaGetSymbolAddress((void**)&wv, g_wv);
    cudaGetSymbolAddress((void**)&wo, g_wo);
    cudaGetSymbolAddress((void**)&qp, g_q);
    cudaGetSymbolAddress((void**)&kp, g_k);
    cudaGetSymbolAddress((void**)&vp, g_v);
    cudaGetSymbolAddress((void**)&ot, g_ot);

    cudaFuncSetAttribute(flash_mma, cudaFuncAttributeMaxDynamicSharedMemorySize, FL_SMEM);
    cudaFuncSetAttribute(qkv_gemm, cudaFuncAttributeMaxDynamicSharedMemorySize, GEMM_SMEM);
    cudaFuncSetAttribute(out_gemm, cudaFuncAttributeMaxDynamicSharedMemorySize, GEMM_SMEM);

    // Convert x + 4 weights to fp16 (one launch; y=4,5 are x halves)
    {
        int n4w = DIM_ * DIM_ / 4;
        dim3 g(n4w / 256, 6);
        conv_all_kernel<<<g, 256>>>(x, Wq, Wk, Wv, Wo, xh, wq, wk, wv, wo, n4w);
    }

    // Fused QKV projections — one launch, 1-pass each
    dim3 gqkv(DIM_ / GBN, MROWS / GBM, 3);   // (16, 32, 3) = 1536 CTAs
    qkv_gemm<<<gqkv, 256, GEMM_SMEM>>>(xh, wq, wk, wv, qp, kp, vp, cosb, sinb);

    // Tensor-core causal flash attention -> ot transposed (single fp16)
    dim3 gflash(S_ / 64, H_, B_);            // (32, 16, 2)
    flash_mma<<<gflash, 128, FL_SMEM>>>(qp, kp, vp, ot);

    // Output projection (fp32 out)
    dim3 ggemm(DIM_ / GBN, MROWS / GBM);     // (16, 32)
    out_gemm<<<ggemm, 256, GEMM_SMEM>>>(ot, wo, (float*)d_out);
}

// round 16
// speedup vs baseline: 2.5637x; 1.0040x over previous
#include <cuda_runtime.h>
#include <cuda_fp16.h>
#include <cstdint>
#include <math.h>

// Problem constants
#define B_    2
#define S_    2048
#define DIM_  2048
#define H_    16
#define DH_   128
#define MROWS (B_ * S_)   // 4096

// ---------------------------------------------------------------------------
// Scratch (allocation-free rule: device globals)
// ---------------------------------------------------------------------------
__device__ __half g_x  [MROWS * DIM_];
__device__ __half g_wq [DIM_ * DIM_];
__device__ __half g_wk [DIM_ * DIM_];
__device__ __half g_wv [DIM_ * DIM_];
__device__ __half g_wo [DIM_ * DIM_];
__device__ __half g_q  [MROWS * DIM_];
__device__ __half g_k  [MROWS * DIM_];
__device__ __half g_v  [MROWS * DIM_];
__device__ __half g_ot [MROWS * DIM_];

// ---------------------------------------------------------------------------
// Helpers
// ---------------------------------------------------------------------------
__device__ __forceinline__ uint32_t smem_u32(const void* p) {
    uint32_t a;
    asm("{ .reg .u64 t; cvta.to.shared.u64 t, %1; cvt.u32.u64 %0, t; }" : "=r"(a) : "l"(p));
    return a;
}
__device__ __forceinline__ void cp_async16(uint32_t dst, const void* src) {
    asm volatile("cp.async.cg.shared.global [%0], [%1], 16;" :: "r"(dst), "l"(src));
}
#define CP_COMMIT() asm volatile("cp.async.commit_group;" ::: "memory")
#define CP_WAIT(n)  asm volatile("cp.async.wait_group %0;" :: "n"(n) : "memory")

__device__ __forceinline__ void ldmatrix_x4(uint32_t& r0, uint32_t& r1,
                                            uint32_t& r2, uint32_t& r3, uint32_t addr) {
    asm volatile("ldmatrix.sync.aligned.m8n8.x4.shared.b16 {%0,%1,%2,%3}, [%4];"
                 : "=r"(r0), "=r"(r1), "=r"(r2), "=r"(r3) : "r"(addr));
}
__device__ __forceinline__ void ldmatrix_x4_trans(uint32_t& r0, uint32_t& r1,
                                                  uint32_t& r2, uint32_t& r3, uint32_t addr) {
    asm volatile("ldmatrix.sync.aligned.m8n8.x4.trans.shared.b16 {%0,%1,%2,%3}, [%4];"
                 : "=r"(r0), "=r"(r1), "=r"(r2), "=r"(r3) : "r"(addr));
}
__device__ __forceinline__ void mma_f16(float* c, const uint32_t* a, const uint32_t* b) {
    asm volatile(
        "mma.sync.aligned.m16n8k16.row.col.f32.f16.f16.f32 "
        "{%0,%1,%2,%3}, {%4,%5,%6,%7}, {%8,%9}, {%0,%1,%2,%3};"
        : "+f"(c[0]), "+f"(c[1]), "+f"(c[2]), "+f"(c[3])
        : "r"(a[0]), "r"(a[1]), "r"(a[2]), "r"(a[3]), "r"(b[0]), "r"(b[1]));
}

// Fast exp2 (degree-5 poly on FMA pipe, avoids MUFU bottleneck)
__device__ __forceinline__ float fexp2(float x) {
    x = fmaxf(x, -80.f);
    float f = x + 12582912.f;
    int  n  = __float_as_int(f) - 0x4B400000;
    float r = x - (f - 12582912.f);
    float p =            1.3333558146e-3f;
    p = fmaf(p, r, 9.6181291076e-3f);
    p = fmaf(p, r, 5.5504108665e-2f);
    p = fmaf(p, r, 2.4022650696e-1f);
    p = fmaf(p, r, 6.9314718056e-1f);
    p = fmaf(p, r, 1.0f);
    return __int_as_float(__float_as_int(p) + (n << 23));
}

__device__ __forceinline__ uint32_t pack_h(float x, float y) {
    __half2 h = __float22half2_rn(make_float2(x, y));
    return *(uint32_t*)&h;
}

// copy 16 bytes smem->reg->gmem with only 4B-aligned smem reads
__device__ __forceinline__ void copy16(const __half* src, __half* dst) {
    uint4 v;
    v.x = *(const uint32_t*)(src + 0);
    v.y = *(const uint32_t*)(src + 2);
    v.z = *(const uint32_t*)(src + 4);
    v.w = *(const uint32_t*)(src + 6);
    *(uint4*)dst = v;
}

// ---------------------------------------------------------------------------
// Convert x + 4 weights to fp16 in one grid (blockIdx.y: 0..3 weights, 4..5 x)
// ---------------------------------------------------------------------------
__global__ void conv_all_kernel(const float* __restrict__ x,
                                const float* __restrict__ w0, const float* __restrict__ w1,
                                const float* __restrict__ w2, const float* __restrict__ w3,
                                __half* __restrict__ xh,
                                __half* __restrict__ h0, __half* __restrict__ h1,
                                __half* __restrict__ h2, __half* __restrict__ h3, int n4)
{
    int i = blockIdx.x * blockDim.x + threadIdx.x;
    if (i >= n4) return;
    const float* in; __half* out;
    switch (blockIdx.y) {
        case 0: in = w0; out = h0; break;
        case 1: in = w1; out = h1; break;
        case 2: in = w2; out = h2; break;
        case 3: in = w3; out = h3; break;
        case 4: in = x;            out = xh;            break;
        default: in = x + 4 * (size_t)n4; out = xh + 4 * (size_t)n4; break;
    }
    float4 v = ((const float4*)in)[i];
    ((uint32_t*)out)[2 * i]     = pack_h(v.x, v.y);
    ((uint32_t*)out)[2 * i + 1] = pack_h(v.z, v.w);
}

// ---------------------------------------------------------------------------
// GEMM core: 2-stage, 2 syncs/iter, BK=64, single pass fp16, fp32 accum.
// Stage = A(16KB) + B(16KB); 2 stages = 64KB dynamic smem, 2 CTAs/SM.
// Block 128x128, 256 threads (8 warps = 4M x 2N).
// ---------------------------------------------------------------------------
#define GBM 128
#define GBN 128
#define GBK 64
#define GSTAGE 32768
#define GEMM_SMEM (2 * GSTAGE)
__device__ __forceinline__ uint32_t swg(int r, int c) {
    return (uint32_t)(r * 128 + ((c ^ (r & 7)) << 4));
}

__device__ __forceinline__ void gemm_core(
    const __half* __restrict__ As, const __half* __restrict__ Bs,
    int bm, int bn, int K, char* sm, float acc[2][8][4])
{
    const int tid  = threadIdx.x;
    const int wid  = tid >> 5;
    const int lane = tid & 31;
    const int mbase = (wid & 3) * 32;
    const int nbase = (wid >> 2) * 64;

    const uint32_t sBase = smem_u32(sm);
    const int NIT = K / GBK;          // 32

    auto issue = [&](int it, int buf) {
        const uint32_t st = sBase + (uint32_t)buf * GSTAGE;
        const int k0 = it * GBK;
#pragma unroll
        for (int i = 0; i < 4; i++) {
            int id = i * 256 + tid;
            int r = id >> 3, c = id & 7;
            uint32_t off = swg(r, c);
            cp_async16(st + off,         As + (size_t)(bm + r) * K + k0 + c * 8);
            cp_async16(st + 16384 + off, Bs + (size_t)(bn + r) * K + k0 + c * 8);
        }
        CP_COMMIT();
    };

#pragma unroll
    for (int mt = 0; mt < 2; mt++)
#pragma unroll
        for (int nt = 0; nt < 8; nt++)
#pragma unroll
            for (int e = 0; e < 4; e++) acc[mt][nt][e] = 0.f;

    issue(0, 0);

    for (int it = 0; it < NIT; it++) {
        const int buf = it & 1;
        if (it + 1 < NIT) {
            issue(it + 1, buf ^ 1);
            CP_WAIT(1);
        } else {
            CP_WAIT(0);
        }
        __syncthreads();

        const uint32_t sA = sBase + (uint32_t)buf * GSTAGE;
        const uint32_t sB = sA + 16384;

#pragma unroll
        for (int ks = 0; ks < 4; ks++) {
            uint32_t afr[2][4];
#pragma unroll
            for (int mt = 0; mt < 2; mt++) {
                int row   = mbase + mt * 16 + (lane & 15);
                int chunk = ks * 2 + (lane >> 4);
                ldmatrix_x4(afr[mt][0], afr[mt][1], afr[mt][2], afr[mt][3],
                            sA + swg(row, chunk));
            }
            uint32_t bfr[8][2];
#pragma unroll
            for (int nt2 = 0; nt2 < 4; nt2++) {
                int row   = nbase + nt2 * 16 + ((lane >> 4) << 3) + (lane & 7);
                int chunk = ks * 2 + ((lane >> 3) & 1);
                ldmatrix_x4(bfr[nt2 * 2][0], bfr[nt2 * 2][1],
                            bfr[nt2 * 2 + 1][0], bfr[nt2 * 2 + 1][1],
                            sB + swg(row, chunk));
            }
#pragma unroll
            for (int mt = 0; mt < 2; mt++)
#pragma unroll
                for (int nt = 0; nt < 8; nt++)
                    mma_f16(acc[mt][nt], afr[mt], bfr[nt]);
        }
        __syncthreads();
    }
}

// ---------------------------------------------------------------------------
// Fused QKV GEMM: blockIdx.z selects {Wq(rope), Wk(rope), Wv}.
// Epilogue stages the fp16 tile in smem, then writes coalesced 16B chunks.
// ---------------------------------------------------------------------------
#define QS 130   // staging stride in fp16 (conflict-light, 4B-aligned rows)

__global__ __launch_bounds__(256, 2) void qkv_gemm(
    const __half* __restrict__ xh,
    const __half* __restrict__ wq, const __half* __restrict__ wk,
    const __half* __restrict__ wv,
    __half* __restrict__ qq, __half* __restrict__ kk, __half* __restrict__ vv,
    const float* __restrict__ cosb, const float* __restrict__ sinb)
{
    extern __shared__ __align__(1024) char smq[];

    const int tid = threadIdx.x;
    const int bm = blockIdx.y * GBM;
    const int bn = blockIdx.x * GBN;
    const int z  = blockIdx.z;

    const __half* Bs = (z == 0) ? wq : (z == 1) ? wk : wv;
    __half* out = (z == 0) ? qq : (z == 1) ? kk : vv;

    float acc[2][8][4];
    gemm_core(xh, Bs, bm, bn, DIM_, smq, acc);

    const int lane = tid & 31;
    const int wid  = tid >> 5;
    const int mbase = (wid & 3) * 32;
    const int nbase = (wid >> 2) * 64;
    const int erow = lane >> 2;
    const int ecol = (lane & 3) * 2;

    // stage into smem (gemm smem is free after the mainloop's final sync)
    __half* sq = (__half*)smq;
#pragma unroll
    for (int mt = 0; mt < 2; mt++) {
#pragma unroll
        for (int nt = 0; nt < 8; nt++) {
            const int lrow = mbase + mt * 16 + erow;
            const int lcol = nbase + nt * 8 + ecol;
            const int grow = bm + lrow;
            const int gcol = bn + lcol;
            float v0 = acc[mt][nt][0], v1 = acc[mt][nt][1];
            float v2 = acc[mt][nt][2], v3 = acc[mt][nt][3];
            if (z < 2) {   // RoPE for q and k
                const int fi = (gcol & 127) >> 1;
                const int s0 = grow & (S_ - 1);
                const int s1 = (grow + 8) & (S_ - 1);
                float c0 = cosb[s0 * 64 + fi], n0 = sinb[s0 * 64 + fi];
                float c1 = cosb[s1 * 64 + fi], n1 = sinb[s1 * 64 + fi];
                float r0 = v0 * c0 - v1 * n0, i0 = v0 * n0 + v1 * c0;
                float r1 = v2 * c1 - v3 * n1, i1 = v2 * n1 + v3 * c1;
                v0 = r0; v1 = i0; v2 = r1; v3 = i1;
            }
            *(uint32_t*)(sq + lrow * QS + lcol)       = pack_h(v0, v1);
            *(uint32_t*)(sq + (lrow + 8) * QS + lcol) = pack_h(v2, v3);
        }
    }
    __syncthreads();

    // coalesced copy: row = tid&127, half = tid>>7 (64 fp16 = 128B each)
    {
        const int row  = tid & 127;
        const int half = tid >> 7;
        const __half* src = sq + row * QS + half * 64;
        __half* dst = out + (size_t)(bm + row) * DIM_ + bn + half * 64;
#pragma unroll
        for (int i = 0; i < 8; i++) copy16(src + i * 8, dst + i * 8);
    }
}

// Output projection GEMM (fp32 out; float2 quad stores are already coalesced)
__global__ __launch_bounds__(256, 2) void out_gemm(
    const __half* __restrict__ As, const __half* __restrict__ Bs,
    float* __restrict__ C)
{
    extern __shared__ __align__(1024) char smo[];
    const int bm = blockIdx.y * GBM;
    const int bn = blockIdx.x * GBN;

    float acc[2][8][4];
    gemm_core(As, Bs, bm, bn, DIM_, smo, acc);

    const int lane = threadIdx.x & 31;
    const int wid  = threadIdx.x >> 5;
    const int mbase = (wid & 3) * 32;
    const int nbase = (wid >> 2) * 64;
    const int erow = lane >> 2;
    const int ecol = (lane & 3) * 2;
#pragma unroll
    for (int mt = 0; mt < 2; mt++) {
#pragma unroll
        for (int nt = 0; nt < 8; nt++) {
            const int grow = bm + mbase + mt * 16 + erow;
            const int gcol = bn + nbase + nt * 8 + ecol;
            float* cp0 = C + (size_t)grow * DIM_ + gcol;
            *(float2*)cp0              = make_float2(acc[mt][nt][0], acc[mt][nt][1]);
            *(float2*)(cp0 + 8 * DIM_) = make_float2(acc[mt][nt][2], acc[mt][nt][3]);
        }
    }
}

// ---------------------------------------------------------------------------
// Flash attention: FA2 on tensor cores, fp16 single-pass, kv tiles of 64.
// CTA: 64 q-rows, 4 warps, double-buffered KV.
// smem: Q 16K + 2 stages x (K 16K + V 16K) = 80KB, 2 CTAs/SM.
// Epilogue stages O transposed in smem -> coalesced 128B-row stores.
// ---------------------------------------------------------------------------
#define FL_SMEM 81920
#define SOS 66   // O staging stride in fp16

__device__ __forceinline__ uint32_t fl_off(int r, int c) {
    return (uint32_t)(r * 256 + ((c ^ (r & 7)) << 4));
}

__global__ __launch_bounds__(128, 2) void flash_mma(
    const __half* __restrict__ qq, const __half* __restrict__ kk,
    const __half* __restrict__ vv, __half* __restrict__ ot)
{
    extern __shared__ __align__(1024) char sm8[];
    const uint32_t sQ = smem_u32(sm8);

    const int qb = (int)gridDim.x - 1 - blockIdx.x;   // largest first
    const int h = blockIdx.y, b = blockIdx.z;
    const int qbase = qb * 64;
    const int tid = threadIdx.x, wid = tid >> 5, lane = tid & 31;
    const int mbase = wid * 16;
    const int colbase = h * DH_;
    const size_t rowg0 = ((size_t)b * S_ + qbase) * DIM_ + colbase;

#pragma unroll
    for (int i = 0; i < 8; i++) {
        int idx = i * 128 + tid;
        int r = idx >> 4, c = idx & 15;
        size_t g = rowg0 + (size_t)r * DIM_ + c * 8;
        cp_async16(sQ + fl_off(r, c), qq + g);
    }
    CP_COMMIT();

    const int NT = qb + 1;   // kv tiles of 64

    auto issueKV = [&](int kb, int st) {
        const uint32_t base = sQ + 16384 + st * 32768;
        const size_t krow0 = ((size_t)b * S_ + kb * 64) * DIM_ + colbase;
#pragma unroll
        for (int i = 0; i < 8; i++) {
            int idx = i * 128 + tid;
            int r = idx >> 4, c = idx & 15;
            uint32_t off = fl_off(r, c);
            size_t g = krow0 + (size_t)r * DIM_ + c * 8;
            cp_async16(base + off,         kk + g);
            cp_async16(base + 16384 + off, vv + g);
        }
        CP_COMMIT();
    };

    issueKV(0, 0);

    float m0 = -1e30f, m1 = -1e30f, l0 = 0.f, l1 = 0.f;
    float o[16][4];
#pragma unroll
    for (int nt = 0; nt < 16; nt++)
#pragma unroll
        for (int e = 0; e < 4; e++) o[nt][e] = 0.f;

    const int rA = lane >> 2;
    const int cq = (lane & 3) * 2;
    const float KARG = 0.1275166782f;   // (1/sqrt(128)) * log2(e)

    const int a_r  = (lane & 7) + ((lane >> 3) & 1) * 8;
    const int a_cb = lane >> 4;
    const int bk_r = (lane & 7);
    const int bk_np = lane >> 4;
    const int bk_cb = (lane >> 3) & 1;

    for (int kb = 0; kb < NT; kb++) {
        const int st = kb & 1;
        const uint32_t sK = sQ + 16384 + st * 32768;
        const uint32_t sV = sK + 16384;

        __syncthreads();
        if (kb + 1 < NT) {
            issueKV(kb + 1, st ^ 1);
            CP_WAIT(1);
        } else {
            CP_WAIT(0);
        }
        __syncthreads();

        // ---- S = Q @ K^T (single-pass fp16), 16x64 per warp ----
        float sacc[8][4];
#pragma unroll
        for (int nt = 0; nt < 8; nt++)
#pragma unroll
            for (int e = 0; e < 4; e++) sacc[nt][e] = 0.f;

#pragma unroll
        for (int kkk = 0; kkk < 8; kkk++) {
            uint32_t aq[4], bk[8][2];
            int arow = mbase + a_r;
            int achk = 2 * kkk + a_cb;
            ldmatrix_x4(aq[0], aq[1], aq[2], aq[3], sQ + fl_off(arow, achk));
#pragma unroll
            for (int np = 0; np < 4; np++) {
                int brow = (2 * np + bk_np) * 8 + bk_r;
                int bchk = 2 * kkk + bk_cb;
                ldmatrix_x4(bk[2 * np][0], bk[2 * np][1],
                            bk[2 * np + 1][0], bk[2 * np + 1][1],
                            sK + fl_off(brow, bchk));
            }
#pragma unroll
            for (int nt = 0; nt < 8; nt++) mma_f16(sacc[nt], aq, bk[nt]);
        }

        // ---- causal mask (tiles overlapping diagonal) ----
        if (kb * 64 + 63 > qbase + mbase) {
            int rowA = qbase + mbase + rA, rowB = rowA + 8;
#pragma unroll
            for (int nt = 0; nt < 8; nt++) {
                int c0 = kb * 64 + nt * 8 + cq;
                if (c0     > rowA) sacc[nt][0] = -1e30f;
                if (c0 + 1 > rowA) sacc[nt][1] = -1e30f;
                if (c0     > rowB) sacc[nt][2] = -1e30f;
                if (c0 + 1 > rowB) sacc[nt][3] = -1e30f;
            }
        }

        // ---- online softmax ----
        float tmA = -1e30f, tmB = -1e30f;
#pragma unroll
        for (int nt = 0; nt < 8; nt++) {
            tmA = fmaxf(tmA, fmaxf(sacc[nt][0], sacc[nt][1]));
            tmB = fmaxf(tmB, fmaxf(sacc[nt][2], sacc[nt][3]));
        }
        tmA = fmaxf(tmA, __shfl_xor_sync(0xffffffffu, tmA, 1));
        tmA = fmaxf(tmA, __shfl_xor_sync(0xffffffffu, tmA, 2));
        tmB = fmaxf(tmB, __shfl_xor_sync(0xffffffffu, tmB, 1));
        tmB = fmaxf(tmB, __shfl_xor_sync(0xffffffffu, tmB, 2));

        float alpha0 = 1.f, alpha1 = 1.f;
        bool upd0 = (tmA > m0), upd1 = (tmB > m1);
        if (upd0) { alpha0 = fexp2((m0 - tmA) * KARG); m0 = tmA; }
        if (upd1) { alpha1 = fexp2((m1 - tmB) * KARG); m1 = tmB; }

        float rs0 = 0.f, rs1 = 0.f;
#pragma unroll
        for (int nt = 0; nt < 8; nt++) {
            float p0 = fexp2((sacc[nt][0] - m0) * KARG);
            float p1 = fexp2((sacc[nt][1] - m0) * KARG);
            float p2 = fexp2((sacc[nt][2] - m1) * KARG);
            float p3 = fexp2((sacc[nt][3] - m1) * KARG);
            sacc[nt][0] = p0; sacc[nt][1] = p1; sacc[nt][2] = p2; sacc[nt][3] = p3;
            rs0 += p0 + p1; rs1 += p2 + p3;
        }
        rs0 += __shfl_xor_sync(0xffffffffu, rs0, 1);
        rs0 += __shfl_xor_sync(0xffffffffu, rs0, 2);
        rs1 += __shfl_xor_sync(0xffffffffu, rs1, 1);
        rs1 += __shfl_xor_sync(0xffffffffu, rs1, 2);
        l0 = alpha0 * l0 + rs0;
        l1 = alpha1 * l1 + rs1;

        if (upd0 || upd1) {
#pragma unroll
            for (int nt = 0; nt < 16; nt++) {
                o[nt][0] *= alpha0; o[nt][1] *= alpha0;
                o[nt][2] *= alpha1; o[nt][3] *= alpha1;
            }
        }

        // ---- pack P (single fp16), 4 k-groups of 16 ----
        uint32_t phi[4][4];
#pragma unroll
        for (int kk2 = 0; kk2 < 4; kk2++) {
            phi[kk2][0] = pack_h(sacc[2 * kk2][0],     sacc[2 * kk2][1]);
            phi[kk2][1] = pack_h(sacc[2 * kk2][2],     sacc[2 * kk2][3]);
            phi[kk2][2] = pack_h(sacc[2 * kk2 + 1][0], sacc[2 * kk2 + 1][1]);
            phi[kk2][3] = pack_h(sacc[2 * kk2 + 1][2], sacc[2 * kk2 + 1][3]);
        }

        // ---- O += P @ V (single-pass) ----
#pragma unroll
        for (int kk2 = 0; kk2 < 4; kk2++) {
#pragma unroll
            for (int np = 0; np < 8; np++) {
                uint32_t bv[4];
                int vrow = kk2 * 16 + a_r;
                int vchk = 2 * np + a_cb;
                ldmatrix_x4_trans(bv[0], bv[1], bv[2], bv[3], sV + fl_off(vrow, vchk));
                mma_f16(o[2 * np],     phi[kk2], bv + 0);
                mma_f16(o[2 * np + 1], phi[kk2], bv + 2);
            }
        }
    }

    // ---- epilogue: stage O as [col][s] in smem, then coalesced stores ----
    __syncthreads();   // all warps done with K/V smem
    __half* so = (__half*)sm8;
    const float inv0 = 1.f / l0, inv1 = 1.f / l1;
    const int sloc0 = mbase + rA;        // local s in [0,64)
    const int sloc1 = sloc0 + 8;
#pragma unroll
    for (int nt = 0; nt < 16; nt++) {
        int cl = nt * 8 + cq;            // local col (even)
        so[(cl    ) * SOS + sloc0] = __float2half_rn(o[nt][0] * inv0);
        so[(cl + 1) * SOS + sloc0] = __float2half_rn(o[nt][1] * inv0);
        so[(cl    ) * SOS + sloc1] = __float2half_rn(o[nt][2] * inv1);
        so[(cl + 1) * SOS + sloc1] = __float2half_rn(o[nt][3] * inv1);
    }
    __syncthreads();
    // thread tid copies col row tid: 64 fp16 = 128B contiguous in ot
    {
        const __half* src = so + tid * SOS;
        __half* dst = ot + ((size_t)b * DIM_ + colbase + tid) * S_ + qbase;
#pragma unroll
        for (int i = 0; i < 8; i++) copy16(src + i * 8, dst + i * 8);
    }
}

// ---------------------------------------------------------------------------
// Launch
// ---------------------------------------------------------------------------
extern "C" void kernel_launch(void* const* d_in, const int* in_sizes, int n_in,
                              void* d_out, int out_size)
{
    const float* x    = (const float*)d_in[0];
    const float* Wq   = (const float*)d_in[1];
    const float* Wk   = (const float*)d_in[2];
    const float* Wv   = (const float*)d_in[3];
    const float* Wo   = (const float*)d_in[4];
    const float* cosb = (const float*)d_in[5];
    const float* sinb = (const float*)d_in[6];
    // d_in[7] = mask: causal handled analytically

    __half *xh, *wq, *wk, *wv, *wo, *qp, *kp, *vp, *ot;
    cudaGetSymbolAddress((void**)&xh, g_x);
    cudaGetSymbolAddress((void**)&wq, g_wq);
    cudaGetSymbolAddress((void**)&wk, g_wk);
    cudaGetSymbolAddress((void**)&wv, g_wv);
    cudaGetSymbolAddress((void**)&wo, g_wo);
    cudaGetSymbolAddress((void**)&qp, g_q);
    cudaGetSymbolAddress((void**)&kp, g_k);
    cudaGetSymbolAddress((void**)&vp, g_v);
    cudaGetSymbolAddress((void**)&ot, g_ot);

    cudaFuncSetAttribute(flash_mma, cudaFuncAttributeMaxDynamicSharedMemorySize, FL_SMEM);
    cudaFuncSetAttribute(qkv_gemm, cudaFuncAttributeMaxDynamicSharedMemorySize, GEMM_SMEM);
    cudaFuncSetAttribute(out_gemm, cudaFuncAttributeMaxDynamicSharedMemorySize, GEMM_SMEM);

    // Convert x + 4 weights to fp16 (one launch; y=4,5 are x halves)
    {
        int n4w = DIM_ * DIM_ / 4;
        dim3 g(n4w / 256, 6);
        conv_all_kernel<<<g, 256>>>(x, Wq, Wk, Wv, Wo, xh, wq, wk, wv, wo, n4w);
    }

    // Fused QKV projections — one launch, 1-pass each
    dim3 gqkv(DIM_ / GBN, MROWS / GBM, 3);   // (16, 32, 3) = 1536 CTAs
    qkv_gemm<<<gqkv, 256, GEMM_SMEM>>>(xh, wq, wk, wv, qp, kp, vp, cosb, sinb);

    // Tensor-core causal flash attention -> ot transposed (single fp16)
    dim3 gflash(S_ / 64, H_, B_);            // (32, 16, 2)
    flash_mma<<<gflash, 128, FL_SMEM>>>(qp, kp, vp, ot);

    // Output projection (fp32 out)
    dim3 ggemm(DIM_ / GBN, MROWS / GBM);     // (16, 32)
    out_gemm<<<ggemm, 256, GEMM_SMEM>>>(ot, wo, (float*)d_out);
}